// round 1
// baseline (speedup 1.0000x reference)
#include <cuda_runtime.h>
#include <math.h>

#define N_NODES 100000
#define N_EDGES 1600000
#define CCH 128
#define C2  256

// Scratch (device globals — no allocation allowed)
__device__ float g_feat[(size_t)N_NODES * C2];   // g = (x@[Wa|Wc]) * dinv[row]
__device__ float g_acc [(size_t)N_NODES * C2];   // accumulator, init = g (self loop)
__device__ int   g_deg [N_NODES];
__device__ float g_dinv[N_NODES];
__device__ float g_csum[CCH];

// ---------------------------------------------------------------- init
__global__ void k_init() {
    int i = blockIdx.x * blockDim.x + threadIdx.x;
    if (i < N_NODES) g_deg[i] = 1;          // self loop
    if (i < CCH)     g_csum[i] = 0.f;
}

__global__ void k_degree(const int* __restrict__ dst) {
    int i = blockIdx.x * blockDim.x + threadIdx.x;
    if (i < N_EDGES) atomicAdd(&g_deg[dst[i]], 1);
}

__global__ void k_dinv() {
    int i = blockIdx.x * blockDim.x + threadIdx.x;
    if (i < N_NODES) g_dinv[i] = rsqrtf((float)g_deg[i]);
}

// ---------------------------------------------------------------- GEMM
// h[N,256] = x[N,128] @ [Wa | Wc]; writes g = h*dinv and acc = g.
// 64x64 tile, 256 threads, 4x4 per-thread microtile.
__global__ void k_gemm(const float* __restrict__ x,
                       const float* __restrict__ Wa,
                       const float* __restrict__ Wc)
{
    __shared__ float As[16][64];
    __shared__ float Bs[16][68];

    const int bm = blockIdx.x * 64;
    const int bn = blockIdx.y * 64;           // 0,64,128,192
    const int tid = threadIdx.x;
    const int ty = tid >> 4, tx = tid & 15;

    const float* W = (bn < CCH) ? Wa : Wc;
    const int wcol = (bn < CCH) ? bn : (bn - CCH);

    const int lm  = tid >> 2;                 // 0..63 (row within tile)
    const int lk  = (tid & 3) * 4;            // 0,4,8,12
    const int bkr = tid >> 4;                 // 0..15
    const int bc  = (tid & 15) * 4;           // 0..60

    float acc[4][4];
#pragma unroll
    for (int i = 0; i < 4; i++)
#pragma unroll
        for (int j = 0; j < 4; j++) acc[i][j] = 0.f;

    for (int k0 = 0; k0 < CCH; k0 += 16) {
        {
            int row = bm + lm;
            float4 v = make_float4(0.f, 0.f, 0.f, 0.f);
            if (row < N_NODES)
                v = *reinterpret_cast<const float4*>(&x[(size_t)row * CCH + k0 + lk]);
            As[lk + 0][lm] = v.x; As[lk + 1][lm] = v.y;
            As[lk + 2][lm] = v.z; As[lk + 3][lm] = v.w;
        }
        {
            float4 w4 = *reinterpret_cast<const float4*>(&W[(size_t)(k0 + bkr) * CCH + wcol + bc]);
            Bs[bkr][bc + 0] = w4.x; Bs[bkr][bc + 1] = w4.y;
            Bs[bkr][bc + 2] = w4.z; Bs[bkr][bc + 3] = w4.w;
        }
        __syncthreads();
#pragma unroll
        for (int kk = 0; kk < 16; kk++) {
            float a[4], b[4];
#pragma unroll
            for (int i = 0; i < 4; i++) a[i] = As[kk][ty * 4 + i];
#pragma unroll
            for (int j = 0; j < 4; j++) b[j] = Bs[kk][tx * 4 + j];
#pragma unroll
            for (int i = 0; i < 4; i++)
#pragma unroll
                for (int j = 0; j < 4; j++)
                    acc[i][j] = fmaf(a[i], b[j], acc[i][j]);
        }
        __syncthreads();
    }

#pragma unroll
    for (int i = 0; i < 4; i++) {
        int row = bm + ty * 4 + i;
        if (row >= N_NODES) continue;
        float dv = g_dinv[row];
#pragma unroll
        for (int j = 0; j < 4; j++) {
            float val = acc[i][j] * dv;
            size_t o = (size_t)row * C2 + bn + tx * 4 + j;
            g_feat[o] = val;
            g_acc[o]  = val;
        }
    }
}

// ---------------------------------------------------------------- edge scatter
// One warp per edge: acc[dst] += g[src]  (256 floats = 2 float4 per lane)
__global__ void k_scatter(const int* __restrict__ src, const int* __restrict__ dst) {
    int w = (blockIdx.x * blockDim.x + threadIdx.x) >> 5;
    int lane = threadIdx.x & 31;
    if (w >= N_EDGES) return;
    int s = __ldg(&src[w]);
    int d = __ldg(&dst[w]);
    const float4* gp = reinterpret_cast<const float4*>(g_feat) + (size_t)s * 64;
    float4*       ap = reinterpret_cast<float4*>(g_acc)  + (size_t)d * 64;
    float4 v0 = __ldg(&gp[lane]);
    float4 v1 = __ldg(&gp[lane + 32]);
    atomicAdd(&ap[lane],      v0);   // sm_90+ vector RED, return ignored
    atomicAdd(&ap[lane + 32], v1);
}

// ---------------------------------------------------------------- node epilogue
// conv = dinv*acc + bias; actor: relu+res -> MLP -> softplus heads;
// critic: relu+res -> per-warp partial sum -> block smem -> global RED.
__device__ __forceinline__ float softplus_f(float v) {
    return fmaxf(v, 0.f) + log1pf(expf(-fabsf(v))) + 1e-20f;
}

__global__ void k_epilogue(const float* __restrict__ x,
                           const float* __restrict__ a_conv_b,
                           const float* __restrict__ c_conv_b,
                           const float* __restrict__ W1, const float* __restrict__ b1,
                           const float* __restrict__ W2, const float* __restrict__ b2,
                           const float* __restrict__ W3, const float* __restrict__ b3,
                           float* __restrict__ out)
{
    __shared__ float sW1[CCH * 32];
    __shared__ float sW2[32 * 32];
    __shared__ float sW3[32 * 4];
    __shared__ float sb1[32], sb2[32], sb3[4];
    __shared__ float sab[CCH], scb[CCH];
    __shared__ float scsum[CCH];

    const int tid = threadIdx.x;
    for (int i = tid; i < CCH * 32; i += blockDim.x) sW1[i] = W1[i];
    for (int i = tid; i < 32 * 32;  i += blockDim.x) sW2[i] = W2[i];
    if (tid < 128) { sW3[tid] = W3[tid]; sab[tid] = a_conv_b[tid];
                     scb[tid] = c_conv_b[tid]; scsum[tid] = 0.f; }
    if (tid < 32)  { sb1[tid] = b1[tid]; sb2[tid] = b2[tid]; }
    if (tid < 4)   { sb3[tid] = b3[tid]; }
    __syncthreads();

    const int lane = tid & 31;
    const int warp = tid >> 5;
    const int gw = blockIdx.x * (blockDim.x >> 5) + warp;
    const int nw = gridDim.x * (blockDim.x >> 5);
    const unsigned FULL = 0xffffffffu;

    float cs0 = 0.f, cs1 = 0.f, cs2 = 0.f, cs3 = 0.f;

    for (int node = gw; node < N_NODES; node += nw) {
        const float dv = g_dinv[node];
        const float* ar = g_acc + (size_t)node * C2;
        const float* xr = x + (size_t)node * CCH;

        float x0 = xr[lane], x1 = xr[lane + 32], x2 = xr[lane + 64], x3 = xr[lane + 96];

        float a0 = fmaxf(fmaf(ar[lane      ], dv, sab[lane      ]), 0.f) + x0;
        float a1 = fmaxf(fmaf(ar[lane + 32 ], dv, sab[lane + 32 ]), 0.f) + x1;
        float a2 = fmaxf(fmaf(ar[lane + 64 ], dv, sab[lane + 64 ]), 0.f) + x2;
        float a3 = fmaxf(fmaf(ar[lane + 96 ], dv, sab[lane + 96 ]), 0.f) + x3;

        cs0 += fmaxf(fmaf(ar[lane + 128], dv, scb[lane      ]), 0.f) + x0;
        cs1 += fmaxf(fmaf(ar[lane + 160], dv, scb[lane + 32 ]), 0.f) + x1;
        cs2 += fmaxf(fmaf(ar[lane + 192], dv, scb[lane + 64 ]), 0.f) + x2;
        cs3 += fmaxf(fmaf(ar[lane + 224], dv, scb[lane + 96 ]), 0.f) + x3;

        // actor MLP layer 1: each lane = one hidden unit
        float h1 = sb1[lane];
#pragma unroll
        for (int r = 0; r < 32; r++)
            h1 = fmaf(__shfl_sync(FULL, a0, r), sW1[(r      ) * 32 + lane], h1);
#pragma unroll
        for (int r = 0; r < 32; r++)
            h1 = fmaf(__shfl_sync(FULL, a1, r), sW1[(r + 32 ) * 32 + lane], h1);
#pragma unroll
        for (int r = 0; r < 32; r++)
            h1 = fmaf(__shfl_sync(FULL, a2, r), sW1[(r + 64 ) * 32 + lane], h1);
#pragma unroll
        for (int r = 0; r < 32; r++)
            h1 = fmaf(__shfl_sync(FULL, a3, r), sW1[(r + 96 ) * 32 + lane], h1);
        h1 = fmaxf(h1, 0.f);

        float h2 = sb2[lane];
#pragma unroll
        for (int r = 0; r < 32; r++)
            h2 = fmaf(__shfl_sync(FULL, h1, r), sW2[r * 32 + lane], h2);
        h2 = fmaxf(h2, 0.f);

        float o = (lane < 4) ? sb3[lane] : 0.f;
#pragma unroll
        for (int r = 0; r < 32; r++) {
            float hv = __shfl_sync(FULL, h2, r);
            if (lane < 4) o = fmaf(hv, sW3[r * 4 + lane], o);
        }

        if (lane < 4) {
            float sp = softplus_f(o);
            if (lane == 0) out[node] = sp;
            else           out[N_NODES + (size_t)node * 3 + (lane - 1)] = sp;
        }
    }

    atomicAdd(&scsum[lane      ], cs0);
    atomicAdd(&scsum[lane + 32 ], cs1);
    atomicAdd(&scsum[lane + 64 ], cs2);
    atomicAdd(&scsum[lane + 96 ], cs3);
    __syncthreads();
    if (tid < CCH) atomicAdd(&g_csum[tid], scsum[tid]);
}

// ---------------------------------------------------------------- critic head
__global__ void k_value(const float* __restrict__ W1, const float* __restrict__ b1,
                        const float* __restrict__ W2, const float* __restrict__ b2,
                        const float* __restrict__ W3, const float* __restrict__ b3,
                        float* __restrict__ out)
{
    const int lane = threadIdx.x;   // 32 threads
    const unsigned FULL = 0xffffffffu;
    float c0 = g_csum[lane], c1 = g_csum[lane + 32],
          c2 = g_csum[lane + 64], c3 = g_csum[lane + 96];

    float h1 = b1[lane];
#pragma unroll
    for (int r = 0; r < 32; r++)
        h1 = fmaf(__shfl_sync(FULL, c0, r), W1[(r      ) * 32 + lane], h1);
#pragma unroll
    for (int r = 0; r < 32; r++)
        h1 = fmaf(__shfl_sync(FULL, c1, r), W1[(r + 32 ) * 32 + lane], h1);
#pragma unroll
    for (int r = 0; r < 32; r++)
        h1 = fmaf(__shfl_sync(FULL, c2, r), W1[(r + 64 ) * 32 + lane], h1);
#pragma unroll
    for (int r = 0; r < 32; r++)
        h1 = fmaf(__shfl_sync(FULL, c3, r), W1[(r + 96 ) * 32 + lane], h1);
    h1 = fmaxf(h1, 0.f);

    float h2 = b2[lane];
#pragma unroll
    for (int r = 0; r < 32; r++)
        h2 = fmaf(__shfl_sync(FULL, h1, r), W2[r * 32 + lane], h2);
    h2 = fmaxf(h2, 0.f);

    float p = h2 * W3[lane];
#pragma unroll
    for (int off = 16; off > 0; off >>= 1)
        p += __shfl_xor_sync(FULL, p, off);
    if (lane == 0) out[(size_t)4 * N_NODES] = p + b3[0];
}

// ---------------------------------------------------------------- launch
extern "C" void kernel_launch(void* const* d_in, const int* in_sizes, int n_in,
                              void* d_out, int out_size)
{
    const float* x    = (const float*)d_in[0];
    const int*   ei   = (const int*)  d_in[1];
    const float* aW   = (const float*)d_in[2];
    const float* ab   = (const float*)d_in[3];
    const float* aW1  = (const float*)d_in[4];
    const float* ab1  = (const float*)d_in[5];
    const float* aW2  = (const float*)d_in[6];
    const float* ab2  = (const float*)d_in[7];
    const float* aW3  = (const float*)d_in[8];
    const float* ab3  = (const float*)d_in[9];
    const float* cW   = (const float*)d_in[10];
    const float* cb   = (const float*)d_in[11];
    const float* cW1  = (const float*)d_in[12];
    const float* cb1  = (const float*)d_in[13];
    const float* cW2  = (const float*)d_in[14];
    const float* cb2  = (const float*)d_in[15];
    const float* cW3  = (const float*)d_in[16];
    const float* cb3  = (const float*)d_in[17];
    float* out = (float*)d_out;

    const int* src = ei;
    const int* dst = ei + N_EDGES;

    k_init  <<<(N_NODES + 255) / 256, 256>>>();
    k_degree<<<(N_EDGES + 255) / 256, 256>>>(dst);
    k_dinv  <<<(N_NODES + 255) / 256, 256>>>();

    dim3 ggrid((N_NODES + 63) / 64, 4);
    k_gemm<<<ggrid, 256>>>(x, aW, cW);

    k_scatter<<<N_EDGES / 8, 256>>>(src, dst);   // 8 warps/block, warp per edge

    k_epilogue<<<2048, 256>>>(x, ab, cb, aW1, ab1, aW2, ab2, aW3, ab3, out);

    k_value<<<1, 32>>>(cW1, cb1, cW2, cb2, cW3, cb3, out);
}

// round 2
// speedup vs baseline: 1.3687x; 1.3687x over previous
#include <cuda_runtime.h>
#include <math.h>

#define N_NODES 100000
#define N_EDGES 1600000
#define CCH 128
#define C2  256
#define FULLM 0xffffffffu

// ---------------- device scratch (no allocation allowed) ----------------
__device__ float g_feat[(size_t)N_NODES * C2];   // g = (x@[Wa|Wc]) * dinv[row]
__device__ int   g_deg [N_NODES];                // deg incl. self loop
__device__ float g_dinv[N_NODES];
__device__ int   g_off [N_NODES + 1];            // CSR offsets (in-edges only)
__device__ int   g_cur [N_NODES];                // fill cursors
__device__ int   g_csr [N_EDGES];                // src per dst-sorted edge
__device__ float g_csum[CCH];                    // critic graph readout

// ---------------------------------------------------------------- init
__global__ void k_init() {
    int i = blockIdx.x * blockDim.x + threadIdx.x;
    if (i < N_NODES) g_deg[i] = 1;          // self loop
    if (i < CCH)     g_csum[i] = 0.f;
}

__global__ void k_degree(const int* __restrict__ dst) {
    int i = blockIdx.x * blockDim.x + threadIdx.x;
    if (i < N_EDGES) atomicAdd(&g_deg[dst[i]], 1);
}

__global__ void k_dinv() {
    int i = blockIdx.x * blockDim.x + threadIdx.x;
    if (i < N_NODES) g_dinv[i] = rsqrtf((float)g_deg[i]);
}

// Single-block exclusive scan of (deg-1) -> g_off, g_cur. 1024 threads.
__global__ void k_scan() {
    __shared__ int warp_sums[32];
    const int t = threadIdx.x;
    const int CH = (N_NODES + 1023) / 1024;
    int beg = t * CH;
    int end = beg + CH; if (end > N_NODES) end = N_NODES; if (beg > N_NODES) beg = N_NODES;
    int s = 0;
    for (int i = beg; i < end; i++) s += g_deg[i] - 1;
    int lane = t & 31, wid = t >> 5;
    int v = s;
#pragma unroll
    for (int o = 1; o < 32; o <<= 1) {
        int u = __shfl_up_sync(FULLM, v, o);
        if (lane >= o) v += u;
    }
    if (lane == 31) warp_sums[wid] = v;
    __syncthreads();
    if (wid == 0) {
        int w = warp_sums[lane];
#pragma unroll
        for (int o = 1; o < 32; o <<= 1) {
            int u = __shfl_up_sync(FULLM, w, o);
            if (lane >= o) w += u;
        }
        warp_sums[lane] = w;
    }
    __syncthreads();
    int off = (v - s) + (wid ? warp_sums[wid - 1] : 0);   // exclusive prefix
    for (int i = beg; i < end; i++) {
        g_off[i] = off; g_cur[i] = off;
        off += g_deg[i] - 1;
    }
    if (t == 1023) g_off[N_NODES] = off;
}

__global__ void k_fill(const int* __restrict__ src, const int* __restrict__ dst) {
    int e = blockIdx.x * blockDim.x + threadIdx.x;
    if (e < N_EDGES) {
        int d = dst[e];
        int p = atomicAdd(&g_cur[d], 1);
        g_csr[p] = src[e];
    }
}

// ---------------------------------------------------------------- GEMM
// h[N,256] = x[N,128] @ [Wa | Wc]; writes g_feat = h*dinv[row].
// 128x128 tile, 256 threads, 8x8 microtile, packed f32x2 FMA.

__device__ __forceinline__ unsigned long long pack2(float x, float y) {
    unsigned long long r;
    asm("mov.b64 %0, {%1, %2};" : "=l"(r) : "f"(x), "f"(y));
    return r;
}
__device__ __forceinline__ void fma2(unsigned long long& d,
                                     unsigned long long a, unsigned long long b) {
    asm("fma.rn.f32x2 %0, %1, %2, %0;" : "+l"(d) : "l"(a), "l"(b));
}
__device__ __forceinline__ float2 unpack2(unsigned long long v) {
    float2 f;
    asm("mov.b64 {%0, %1}, %2;" : "=f"(f.x), "=f"(f.y) : "l"(v));
    return f;
}

__global__ __launch_bounds__(256, 2)
void k_gemm(const float* __restrict__ x,
            const float* __restrict__ Wa,
            const float* __restrict__ Wc)
{
    __shared__ float As[16][128];
    __shared__ float Bs[16][128];

    const int bm   = blockIdx.x * 128;
    const int half = blockIdx.y;                 // 0 = actor cols, 1 = critic cols
    const float* W = half ? Wc : Wa;
    const int tid  = threadIdx.x;
    const int tx   = tid & 15, ty = tid >> 4;

    const int lr = tid >> 2;                     // 0..63
    const int lk = (tid & 3) * 4;                // 0,4,8,12
    const int br = tid >> 4;                     // 0..15
    const int bc = (tid & 15) * 8;               // 0..120

    unsigned long long acc[8][4];
#pragma unroll
    for (int i = 0; i < 8; i++)
#pragma unroll
        for (int j = 0; j < 4; j++) acc[i][j] = 0ull;

    for (int k0 = 0; k0 < CCH; k0 += 16) {
#pragma unroll
        for (int h = 0; h < 128; h += 64) {
            int row = bm + lr + h;
            float4 v = make_float4(0.f, 0.f, 0.f, 0.f);
            if (row < N_NODES)
                v = *reinterpret_cast<const float4*>(&x[(size_t)row * CCH + k0 + lk]);
            As[lk + 0][lr + h] = v.x; As[lk + 1][lr + h] = v.y;
            As[lk + 2][lr + h] = v.z; As[lk + 3][lr + h] = v.w;
        }
        *reinterpret_cast<float4*>(&Bs[br][bc]) =
            *reinterpret_cast<const float4*>(&W[(size_t)(k0 + br) * CCH + bc]);
        *reinterpret_cast<float4*>(&Bs[br][bc + 4]) =
            *reinterpret_cast<const float4*>(&W[(size_t)(k0 + br) * CCH + bc + 4]);
        __syncthreads();

#pragma unroll
        for (int kk = 0; kk < 16; kk++) {
            float4 a0 = *reinterpret_cast<const float4*>(&As[kk][ty * 8]);
            float4 a1 = *reinterpret_cast<const float4*>(&As[kk][ty * 8 + 4]);
            float4 b0 = *reinterpret_cast<const float4*>(&Bs[kk][tx * 8]);
            float4 b1 = *reinterpret_cast<const float4*>(&Bs[kk][tx * 8 + 4]);
            unsigned long long bp[4];
            bp[0] = pack2(b0.x, b0.y); bp[1] = pack2(b0.z, b0.w);
            bp[2] = pack2(b1.x, b1.y); bp[3] = pack2(b1.z, b1.w);
            float av[8] = {a0.x, a0.y, a0.z, a0.w, a1.x, a1.y, a1.z, a1.w};
#pragma unroll
            for (int i = 0; i < 8; i++) {
                unsigned long long ap = pack2(av[i], av[i]);
#pragma unroll
                for (int j = 0; j < 4; j++) fma2(acc[i][j], ap, bp[j]);
            }
        }
        __syncthreads();
    }

    const int row0 = bm + ty * 8;
#pragma unroll
    for (int i = 0; i < 8; i++) {
        int row = row0 + i;
        if (row >= N_NODES) continue;
        float dv = g_dinv[row];
        float2 r0 = unpack2(acc[i][0]), r1 = unpack2(acc[i][1]);
        float2 r2 = unpack2(acc[i][2]), r3 = unpack2(acc[i][3]);
        float4 o0 = make_float4(r0.x * dv, r0.y * dv, r1.x * dv, r1.y * dv);
        float4 o1 = make_float4(r2.x * dv, r2.y * dv, r3.x * dv, r3.y * dv);
        size_t base = (size_t)row * C2 + half * CCH + tx * 8;
        *reinterpret_cast<float4*>(&g_feat[base])     = o0;
        *reinterpret_cast<float4*>(&g_feat[base + 4]) = o1;
    }
}

// ---------------------------------------------------------------- fused gather + epilogue
// Warp per node: acc = g[node] + sum_{in-edges} g[src]; conv epilogue; actor MLP;
// critic partial sums. Channel mapping: lane q of float4 -> channel 4*lane+q.
__device__ __forceinline__ float softplus_f(float v) {
    return fmaxf(v, 0.f) + log1pf(expf(-fabsf(v))) + 1e-20f;
}

__global__ void k_aggregate(const float* __restrict__ x,
                            const float* __restrict__ a_conv_b,
                            const float* __restrict__ c_conv_b,
                            const float* __restrict__ W1, const float* __restrict__ b1,
                            const float* __restrict__ W2, const float* __restrict__ b2,
                            const float* __restrict__ W3, const float* __restrict__ b3,
                            float* __restrict__ out)
{
    __shared__ float sW1[CCH * 32];
    __shared__ float sW2[32 * 32];
    __shared__ float sW3[32 * 4];
    __shared__ float sb1[32], sb2[32], sb3[4];
    __shared__ float sab[CCH], scb[CCH];
    __shared__ float scsum[CCH];

    const int tid = threadIdx.x;
    for (int i = tid; i < CCH * 32; i += blockDim.x) sW1[i] = W1[i];
    for (int i = tid; i < 32 * 32;  i += blockDim.x) sW2[i] = W2[i];
    if (tid < 128) { sW3[tid] = W3[tid]; sab[tid] = a_conv_b[tid];
                     scb[tid] = c_conv_b[tid]; scsum[tid] = 0.f; }
    if (tid < 32)  { sb1[tid] = b1[tid]; sb2[tid] = b2[tid]; }
    if (tid < 4)   { sb3[tid] = b3[tid]; }
    __syncthreads();

    const int lane = tid & 31;
    const int warp = tid >> 5;
    const int gw = blockIdx.x * (blockDim.x >> 5) + warp;
    const int nw = gridDim.x * (blockDim.x >> 5);

    float4 cs = make_float4(0.f, 0.f, 0.f, 0.f);

    for (int node = gw; node < N_NODES; node += nw) {
        const float dv = g_dinv[node];
        const float4* self = reinterpret_cast<const float4*>(g_feat) + (size_t)node * 64;
        float4 A = self[lane];            // actor channels 4*lane..+3
        float4 Cc = self[lane + 32];      // critic channels 4*lane..+3

        const int beg = g_off[node], end = g_off[node + 1];
        int j = beg;
        for (; j + 1 < end; j += 2) {
            int s0 = g_csr[j], s1 = g_csr[j + 1];
            const float4* p0 = reinterpret_cast<const float4*>(g_feat) + (size_t)s0 * 64;
            const float4* p1 = reinterpret_cast<const float4*>(g_feat) + (size_t)s1 * 64;
            float4 u0 = p0[lane], u1 = p0[lane + 32];
            float4 v0 = p1[lane], v1 = p1[lane + 32];
            A.x += u0.x; A.y += u0.y; A.z += u0.z; A.w += u0.w;
            Cc.x += u1.x; Cc.y += u1.y; Cc.z += u1.z; Cc.w += u1.w;
            A.x += v0.x; A.y += v0.y; A.z += v0.z; A.w += v0.w;
            Cc.x += v1.x; Cc.y += v1.y; Cc.z += v1.z; Cc.w += v1.w;
        }
        if (j < end) {
            int s0 = g_csr[j];
            const float4* p0 = reinterpret_cast<const float4*>(g_feat) + (size_t)s0 * 64;
            float4 u0 = p0[lane], u1 = p0[lane + 32];
            A.x += u0.x; A.y += u0.y; A.z += u0.z; A.w += u0.w;
            Cc.x += u1.x; Cc.y += u1.y; Cc.z += u1.z; Cc.w += u1.w;
        }

        // conv epilogue: relu(dv*acc + b) + x
        float4 xv = reinterpret_cast<const float4*>(x)[(size_t)node * 32 + lane];
        int c0 = 4 * lane;
        float4 a;
        a.x = fmaxf(fmaf(A.x, dv, sab[c0 + 0]), 0.f) + xv.x;
        a.y = fmaxf(fmaf(A.y, dv, sab[c0 + 1]), 0.f) + xv.y;
        a.z = fmaxf(fmaf(A.z, dv, sab[c0 + 2]), 0.f) + xv.z;
        a.w = fmaxf(fmaf(A.w, dv, sab[c0 + 3]), 0.f) + xv.w;

        cs.x += fmaxf(fmaf(Cc.x, dv, scb[c0 + 0]), 0.f) + xv.x;
        cs.y += fmaxf(fmaf(Cc.y, dv, scb[c0 + 1]), 0.f) + xv.y;
        cs.z += fmaxf(fmaf(Cc.z, dv, scb[c0 + 2]), 0.f) + xv.z;
        cs.w += fmaxf(fmaf(Cc.w, dv, scb[c0 + 3]), 0.f) + xv.w;

        // actor MLP layer 1: lane = hidden unit; channels come 4 per source lane
        float h1 = sb1[lane];
#pragma unroll
        for (int r = 0; r < 32; r++) {
            float axr = __shfl_sync(FULLM, a.x, r);
            float ayr = __shfl_sync(FULLM, a.y, r);
            float azr = __shfl_sync(FULLM, a.z, r);
            float awr = __shfl_sync(FULLM, a.w, r);
            h1 = fmaf(axr, sW1[(4 * r + 0) * 32 + lane], h1);
            h1 = fmaf(ayr, sW1[(4 * r + 1) * 32 + lane], h1);
            h1 = fmaf(azr, sW1[(4 * r + 2) * 32 + lane], h1);
            h1 = fmaf(awr, sW1[(4 * r + 3) * 32 + lane], h1);
        }
        h1 = fmaxf(h1, 0.f);

        float h2 = sb2[lane];
#pragma unroll
        for (int r = 0; r < 32; r++)
            h2 = fmaf(__shfl_sync(FULLM, h1, r), sW2[r * 32 + lane], h2);
        h2 = fmaxf(h2, 0.f);

        float o = (lane < 4) ? sb3[lane] : 0.f;
#pragma unroll
        for (int r = 0; r < 32; r++) {
            float hv = __shfl_sync(FULLM, h2, r);
            if (lane < 4) o = fmaf(hv, sW3[r * 4 + lane], o);
        }

        if (lane < 4) {
            float sp = softplus_f(o);
            if (lane == 0) out[node] = sp;
            else           out[N_NODES + (size_t)node * 3 + (lane - 1)] = sp;
        }
    }

    int c0 = 4 * lane;
    atomicAdd(&scsum[c0 + 0], cs.x);
    atomicAdd(&scsum[c0 + 1], cs.y);
    atomicAdd(&scsum[c0 + 2], cs.z);
    atomicAdd(&scsum[c0 + 3], cs.w);
    __syncthreads();
    if (tid < CCH) atomicAdd(&g_csum[tid], scsum[tid]);
}

// ---------------------------------------------------------------- critic head
__global__ void k_value(const float* __restrict__ W1, const float* __restrict__ b1,
                        const float* __restrict__ W2, const float* __restrict__ b2,
                        const float* __restrict__ W3, const float* __restrict__ b3,
                        float* __restrict__ out)
{
    const int lane = threadIdx.x;   // 32 threads
    float c0 = g_csum[lane], c1 = g_csum[lane + 32],
          c2 = g_csum[lane + 64], c3 = g_csum[lane + 96];

    float h1 = b1[lane];
#pragma unroll
    for (int r = 0; r < 32; r++)
        h1 = fmaf(__shfl_sync(FULLM, c0, r), W1[(r      ) * 32 + lane], h1);
#pragma unroll
    for (int r = 0; r < 32; r++)
        h1 = fmaf(__shfl_sync(FULLM, c1, r), W1[(r + 32 ) * 32 + lane], h1);
#pragma unroll
    for (int r = 0; r < 32; r++)
        h1 = fmaf(__shfl_sync(FULLM, c2, r), W1[(r + 64 ) * 32 + lane], h1);
#pragma unroll
    for (int r = 0; r < 32; r++)
        h1 = fmaf(__shfl_sync(FULLM, c3, r), W1[(r + 96 ) * 32 + lane], h1);
    h1 = fmaxf(h1, 0.f);

    float h2 = b2[lane];
#pragma unroll
    for (int r = 0; r < 32; r++)
        h2 = fmaf(__shfl_sync(FULLM, h1, r), W2[r * 32 + lane], h2);
    h2 = fmaxf(h2, 0.f);

    float p = h2 * W3[lane];
#pragma unroll
    for (int off = 16; off > 0; off >>= 1)
        p += __shfl_xor_sync(FULLM, p, off);
    if (lane == 0) out[(size_t)4 * N_NODES] = p + b3[0];
}

// ---------------------------------------------------------------- launch
extern "C" void kernel_launch(void* const* d_in, const int* in_sizes, int n_in,
                              void* d_out, int out_size)
{
    const float* x    = (const float*)d_in[0];
    const int*   ei   = (const int*)  d_in[1];
    const float* aW   = (const float*)d_in[2];
    const float* ab   = (const float*)d_in[3];
    const float* aW1  = (const float*)d_in[4];
    const float* ab1  = (const float*)d_in[5];
    const float* aW2  = (const float*)d_in[6];
    const float* ab2  = (const float*)d_in[7];
    const float* aW3  = (const float*)d_in[8];
    const float* ab3  = (const float*)d_in[9];
    const float* cW   = (const float*)d_in[10];
    const float* cb   = (const float*)d_in[11];
    const float* cW1  = (const float*)d_in[12];
    const float* cb1  = (const float*)d_in[13];
    const float* cW2  = (const float*)d_in[14];
    const float* cb2  = (const float*)d_in[15];
    const float* cW3  = (const float*)d_in[16];
    const float* cb3  = (const float*)d_in[17];
    float* out = (float*)d_out;

    const int* src = ei;
    const int* dst = ei + N_EDGES;

    k_init  <<<(N_NODES + 255) / 256, 256>>>();
    k_degree<<<(N_EDGES + 255) / 256, 256>>>(dst);
    k_dinv  <<<(N_NODES + 255) / 256, 256>>>();
    k_scan  <<<1, 1024>>>();
    k_fill  <<<(N_EDGES + 255) / 256, 256>>>(src, dst);

    dim3 ggrid((N_NODES + 127) / 128, 2);
    k_gemm<<<ggrid, 256>>>(x, aW, cW);

    k_aggregate<<<2048, 256>>>(x, ab, cb, aW1, ab1, aW2, ab2, aW3, ab3, out);

    k_value<<<1, 32>>>(cW1, cb1, cW2, cb2, cW3, cb3, out);
}

// round 3
// speedup vs baseline: 1.8343x; 1.3402x over previous
#include <cuda_runtime.h>
#include <math.h>

#define N_NODES 100000
#define N_EDGES 1600000
#define CCH 128
#define C2  256
#define FULLM 0xffffffffu
#define SCAN_B 1024
#define SCAN_G ((N_NODES + SCAN_B - 1) / SCAN_B)   // 98

// ---------------- device scratch (no allocation allowed) ----------------
__device__ float g_feat[(size_t)N_NODES * C2];   // g = (x@[Wa|Wc]) * dinv[row]
__device__ int   g_deg [N_NODES];                // deg incl. self loop
__device__ float g_dinv[N_NODES];
__device__ int   g_off [N_NODES + 1];            // CSR offsets (in-edges only)
__device__ int   g_cur [N_NODES];                // fill cursors
__device__ int   g_csr [N_EDGES];                // src per dst-sorted edge
__device__ int   g_bsum[SCAN_G];                 // per-block sums for scan
__device__ float g_csum[CCH];                    // critic graph readout

// ---------------------------------------------------------------- init
__global__ void k_init() {
    int i = blockIdx.x * blockDim.x + threadIdx.x;
    if (i < N_NODES) g_deg[i] = 1;          // self loop
    if (i < CCH)     g_csum[i] = 0.f;
}

__global__ void k_degree(const int* __restrict__ dst) {
    int i = blockIdx.x * blockDim.x + threadIdx.x;
    if (i < N_EDGES) atomicAdd(&g_deg[dst[i]], 1);
}

__global__ void k_dinv() {
    int i = blockIdx.x * blockDim.x + threadIdx.x;
    if (i < N_NODES) g_dinv[i] = rsqrtf((float)g_deg[i]);
}

// ---------------- 3-phase parallel exclusive scan of (deg-1) ----------------
__device__ __forceinline__ int block_excl_scan(int v, int lane, int wid, int* warp_sums, int nwarp) {
    // returns exclusive prefix of v within block; warp_sums is smem[32]
    int inc = v;
#pragma unroll
    for (int o = 1; o < 32; o <<= 1) {
        int u = __shfl_up_sync(FULLM, inc, o);
        if (lane >= o) inc += u;
    }
    if (lane == 31) warp_sums[wid] = inc;
    __syncthreads();
    if (wid == 0) {
        int w = (lane < nwarp) ? warp_sums[lane] : 0;
#pragma unroll
        for (int o = 1; o < 32; o <<= 1) {
            int u = __shfl_up_sync(FULLM, w, o);
            if (lane >= o) w += u;
        }
        warp_sums[lane] = w;
    }
    __syncthreads();
    return (inc - v) + (wid ? warp_sums[wid - 1] : 0);
}

// Phase 1: per-block local exclusive scan into g_off; block sum into g_bsum.
__global__ void k_scan1() {
    __shared__ int warp_sums[32];
    int i = blockIdx.x * SCAN_B + threadIdx.x;
    int d = (i < N_NODES) ? (g_deg[i] - 1) : 0;
    int ex = block_excl_scan(d, threadIdx.x & 31, threadIdx.x >> 5, warp_sums, SCAN_B / 32);
    if (i < N_NODES) g_off[i] = ex;
    if (threadIdx.x == SCAN_B - 1) g_bsum[blockIdx.x] = ex + d;
}

// Phase 2: single block scans the SCAN_G block sums (exclusive, in place).
__global__ void k_scan2() {
    __shared__ int warp_sums[32];
    int t = threadIdx.x;                    // 128 threads >= SCAN_G
    int v = (t < SCAN_G) ? g_bsum[t] : 0;
    int ex = block_excl_scan(v, t & 31, t >> 5, warp_sums, 4);
    if (t < SCAN_G) g_bsum[t] = ex;
}

// Phase 3: add block offsets; init cursors; sentinel.
__global__ void k_scan3() {
    int i = blockIdx.x * SCAN_B + threadIdx.x;
    if (i < N_NODES) {
        int o = g_off[i] + g_bsum[blockIdx.x];
        g_off[i] = o;
        g_cur[i] = o;
    }
    if (i == 0) g_off[N_NODES] = N_EDGES;   // sum of (deg-1) == E analytically
}

__global__ void k_fill(const int* __restrict__ src, const int* __restrict__ dst) {
    int e = blockIdx.x * blockDim.x + threadIdx.x;
    if (e < N_EDGES) {
        int d = dst[e];
        int p = atomicAdd(&g_cur[d], 1);
        g_csr[p] = src[e];
    }
}

// ---------------------------------------------------------------- GEMM
// h[N,256] = x[N,128] @ [Wa | Wc]; writes g_feat = h*dinv[row].
// 128x128 tile, 256 threads, 8x8 microtile, packed f32x2 FMA.

__device__ __forceinline__ unsigned long long pack2(float x, float y) {
    unsigned long long r;
    asm("mov.b64 %0, {%1, %2};" : "=l"(r) : "f"(x), "f"(y));
    return r;
}
__device__ __forceinline__ void fma2(unsigned long long& d,
                                     unsigned long long a, unsigned long long b) {
    asm("fma.rn.f32x2 %0, %1, %2, %0;" : "+l"(d) : "l"(a), "l"(b));
}
__device__ __forceinline__ float2 unpack2(unsigned long long v) {
    float2 f;
    asm("mov.b64 {%0, %1}, %2;" : "=f"(f.x), "=f"(f.y) : "l"(v));
    return f;
}

__global__ __launch_bounds__(256, 2)
void k_gemm(const float* __restrict__ x,
            const float* __restrict__ Wa,
            const float* __restrict__ Wc)
{
    __shared__ float As[16][128];
    __shared__ float Bs[16][128];

    const int bm   = blockIdx.x * 128;
    const int half = blockIdx.y;                 // 0 = actor cols, 1 = critic cols
    const float* W = half ? Wc : Wa;
    const int tid  = threadIdx.x;
    const int tx   = tid & 15, ty = tid >> 4;

    const int lr = tid >> 2;                     // 0..63
    const int lk = (tid & 3) * 4;                // 0,4,8,12
    const int br = tid >> 4;                     // 0..15
    const int bc = (tid & 15) * 8;               // 0..120

    unsigned long long acc[8][4];
#pragma unroll
    for (int i = 0; i < 8; i++)
#pragma unroll
        for (int j = 0; j < 4; j++) acc[i][j] = 0ull;

    for (int k0 = 0; k0 < CCH; k0 += 16) {
#pragma unroll
        for (int h = 0; h < 128; h += 64) {
            int row = bm + lr + h;
            float4 v = make_float4(0.f, 0.f, 0.f, 0.f);
            if (row < N_NODES)
                v = *reinterpret_cast<const float4*>(&x[(size_t)row * CCH + k0 + lk]);
            As[lk + 0][lr + h] = v.x; As[lk + 1][lr + h] = v.y;
            As[lk + 2][lr + h] = v.z; As[lk + 3][lr + h] = v.w;
        }
        *reinterpret_cast<float4*>(&Bs[br][bc]) =
            *reinterpret_cast<const float4*>(&W[(size_t)(k0 + br) * CCH + bc]);
        *reinterpret_cast<float4*>(&Bs[br][bc + 4]) =
            *reinterpret_cast<const float4*>(&W[(size_t)(k0 + br) * CCH + bc + 4]);
        __syncthreads();

#pragma unroll
        for (int kk = 0; kk < 16; kk++) {
            float4 a0 = *reinterpret_cast<const float4*>(&As[kk][ty * 8]);
            float4 a1 = *reinterpret_cast<const float4*>(&As[kk][ty * 8 + 4]);
            float4 b0 = *reinterpret_cast<const float4*>(&Bs[kk][tx * 8]);
            float4 b1 = *reinterpret_cast<const float4*>(&Bs[kk][tx * 8 + 4]);
            unsigned long long bp[4];
            bp[0] = pack2(b0.x, b0.y); bp[1] = pack2(b0.z, b0.w);
            bp[2] = pack2(b1.x, b1.y); bp[3] = pack2(b1.z, b1.w);
            float av[8] = {a0.x, a0.y, a0.z, a0.w, a1.x, a1.y, a1.z, a1.w};
#pragma unroll
            for (int i = 0; i < 8; i++) {
                unsigned long long ap = pack2(av[i], av[i]);
#pragma unroll
                for (int j = 0; j < 4; j++) fma2(acc[i][j], ap, bp[j]);
            }
        }
        __syncthreads();
    }

    const int row0 = bm + ty * 8;
#pragma unroll
    for (int i = 0; i < 8; i++) {
        int row = row0 + i;
        if (row >= N_NODES) continue;
        float dv = g_dinv[row];
        float2 r0 = unpack2(acc[i][0]), r1 = unpack2(acc[i][1]);
        float2 r2 = unpack2(acc[i][2]), r3 = unpack2(acc[i][3]);
        float4 o0 = make_float4(r0.x * dv, r0.y * dv, r1.x * dv, r1.y * dv);
        float4 o1 = make_float4(r2.x * dv, r2.y * dv, r3.x * dv, r3.y * dv);
        size_t base = (size_t)row * C2 + half * CCH + tx * 8;
        *reinterpret_cast<float4*>(&g_feat[base])     = o0;
        *reinterpret_cast<float4*>(&g_feat[base + 4]) = o1;
    }
}

// ---------------------------------------------------------------- fused gather + epilogue
__device__ __forceinline__ float softplus_f(float v) {
    return fmaxf(v, 0.f) + log1pf(expf(-fabsf(v))) + 1e-20f;
}

__global__ void k_aggregate(const float* __restrict__ x,
                            const float* __restrict__ a_conv_b,
                            const float* __restrict__ c_conv_b,
                            const float* __restrict__ W1, const float* __restrict__ b1,
                            const float* __restrict__ W2, const float* __restrict__ b2,
                            const float* __restrict__ W3, const float* __restrict__ b3,
                            float* __restrict__ out)
{
    __shared__ float sW1[CCH * 32];
    __shared__ float sW2[32 * 32];
    __shared__ float sW3[32 * 4];
    __shared__ float sb1[32], sb2[32], sb3[4];
    __shared__ float sab[CCH], scb[CCH];
    __shared__ float scsum[CCH];

    const int tid = threadIdx.x;
    for (int i = tid; i < CCH * 32; i += blockDim.x) sW1[i] = W1[i];
    for (int i = tid; i < 32 * 32;  i += blockDim.x) sW2[i] = W2[i];
    if (tid < 128) { sW3[tid] = W3[tid]; sab[tid] = a_conv_b[tid];
                     scb[tid] = c_conv_b[tid]; scsum[tid] = 0.f; }
    if (tid < 32)  { sb1[tid] = b1[tid]; sb2[tid] = b2[tid]; }
    if (tid < 4)   { sb3[tid] = b3[tid]; }
    __syncthreads();

    const int lane = tid & 31;
    const int warp = tid >> 5;
    const int gw = blockIdx.x * (blockDim.x >> 5) + warp;
    const int nw = gridDim.x * (blockDim.x >> 5);

    float4 cs = make_float4(0.f, 0.f, 0.f, 0.f);

    for (int node = gw; node < N_NODES; node += nw) {
        const float dv = g_dinv[node];
        const float4* self = reinterpret_cast<const float4*>(g_feat) + (size_t)node * 64;
        float4 A = self[lane];            // actor channels 4*lane..+3
        float4 Cc = self[lane + 32];      // critic channels 4*lane..+3

        const int beg = g_off[node], end = g_off[node + 1];
        int j = beg;
        for (; j + 1 < end; j += 2) {
            int s0 = g_csr[j], s1 = g_csr[j + 1];
            const float4* p0 = reinterpret_cast<const float4*>(g_feat) + (size_t)s0 * 64;
            const float4* p1 = reinterpret_cast<const float4*>(g_feat) + (size_t)s1 * 64;
            float4 u0 = p0[lane], u1 = p0[lane + 32];
            float4 v0 = p1[lane], v1 = p1[lane + 32];
            A.x += u0.x; A.y += u0.y; A.z += u0.z; A.w += u0.w;
            Cc.x += u1.x; Cc.y += u1.y; Cc.z += u1.z; Cc.w += u1.w;
            A.x += v0.x; A.y += v0.y; A.z += v0.z; A.w += v0.w;
            Cc.x += v1.x; Cc.y += v1.y; Cc.z += v1.z; Cc.w += v1.w;
        }
        if (j < end) {
            int s0 = g_csr[j];
            const float4* p0 = reinterpret_cast<const float4*>(g_feat) + (size_t)s0 * 64;
            float4 u0 = p0[lane], u1 = p0[lane + 32];
            A.x += u0.x; A.y += u0.y; A.z += u0.z; A.w += u0.w;
            Cc.x += u1.x; Cc.y += u1.y; Cc.z += u1.z; Cc.w += u1.w;
        }

        float4 xv = reinterpret_cast<const float4*>(x)[(size_t)node * 32 + lane];
        int c0 = 4 * lane;
        float4 a;
        a.x = fmaxf(fmaf(A.x, dv, sab[c0 + 0]), 0.f) + xv.x;
        a.y = fmaxf(fmaf(A.y, dv, sab[c0 + 1]), 0.f) + xv.y;
        a.z = fmaxf(fmaf(A.z, dv, sab[c0 + 2]), 0.f) + xv.z;
        a.w = fmaxf(fmaf(A.w, dv, sab[c0 + 3]), 0.f) + xv.w;

        cs.x += fmaxf(fmaf(Cc.x, dv, scb[c0 + 0]), 0.f) + xv.x;
        cs.y += fmaxf(fmaf(Cc.y, dv, scb[c0 + 1]), 0.f) + xv.y;
        cs.z += fmaxf(fmaf(Cc.z, dv, scb[c0 + 2]), 0.f) + xv.z;
        cs.w += fmaxf(fmaf(Cc.w, dv, scb[c0 + 3]), 0.f) + xv.w;

        float h1 = sb1[lane];
#pragma unroll
        for (int r = 0; r < 32; r++) {
            float axr = __shfl_sync(FULLM, a.x, r);
            float ayr = __shfl_sync(FULLM, a.y, r);
            float azr = __shfl_sync(FULLM, a.z, r);
            float awr = __shfl_sync(FULLM, a.w, r);
            h1 = fmaf(axr, sW1[(4 * r + 0) * 32 + lane], h1);
            h1 = fmaf(ayr, sW1[(4 * r + 1) * 32 + lane], h1);
            h1 = fmaf(azr, sW1[(4 * r + 2) * 32 + lane], h1);
            h1 = fmaf(awr, sW1[(4 * r + 3) * 32 + lane], h1);
        }
        h1 = fmaxf(h1, 0.f);

        float h2 = sb2[lane];
#pragma unroll
        for (int r = 0; r < 32; r++)
            h2 = fmaf(__shfl_sync(FULLM, h1, r), sW2[r * 32 + lane], h2);
        h2 = fmaxf(h2, 0.f);

        float o = (lane < 4) ? sb3[lane] : 0.f;
#pragma unroll
        for (int r = 0; r < 32; r++) {
            float hv = __shfl_sync(FULLM, h2, r);
            if (lane < 4) o = fmaf(hv, sW3[r * 4 + lane], o);
        }

        if (lane < 4) {
            float sp = softplus_f(o);
            if (lane == 0) out[node] = sp;
            else           out[N_NODES + (size_t)node * 3 + (lane - 1)] = sp;
        }
    }

    int c0 = 4 * lane;
    atomicAdd(&scsum[c0 + 0], cs.x);
    atomicAdd(&scsum[c0 + 1], cs.y);
    atomicAdd(&scsum[c0 + 2], cs.z);
    atomicAdd(&scsum[c0 + 3], cs.w);
    __syncthreads();
    if (tid < CCH) atomicAdd(&g_csum[tid], scsum[tid]);
}

// ---------------------------------------------------------------- critic head
__global__ void k_value(const float* __restrict__ W1, const float* __restrict__ b1,
                        const float* __restrict__ W2, const float* __restrict__ b2,
                        const float* __restrict__ W3, const float* __restrict__ b3,
                        float* __restrict__ out)
{
    const int lane = threadIdx.x;   // 32 threads
    float c0 = g_csum[lane], c1 = g_csum[lane + 32],
          c2 = g_csum[lane + 64], c3 = g_csum[lane + 96];

    float h1 = b1[lane];
#pragma unroll
    for (int r = 0; r < 32; r++)
        h1 = fmaf(__shfl_sync(FULLM, c0, r), W1[(r      ) * 32 + lane], h1);
#pragma unroll
    for (int r = 0; r < 32; r++)
        h1 = fmaf(__shfl_sync(FULLM, c1, r), W1[(r + 32 ) * 32 + lane], h1);
#pragma unroll
    for (int r = 0; r < 32; r++)
        h1 = fmaf(__shfl_sync(FULLM, c2, r), W1[(r + 64 ) * 32 + lane], h1);
#pragma unroll
    for (int r = 0; r < 32; r++)
        h1 = fmaf(__shfl_sync(FULLM, c3, r), W1[(r + 96 ) * 32 + lane], h1);
    h1 = fmaxf(h1, 0.f);

    float h2 = b2[lane];
#pragma unroll
    for (int r = 0; r < 32; r++)
        h2 = fmaf(__shfl_sync(FULLM, h1, r), W2[r * 32 + lane], h2);
    h2 = fmaxf(h2, 0.f);

    float p = h2 * W3[lane];
#pragma unroll
    for (int off = 16; off > 0; off >>= 1)
        p += __shfl_xor_sync(FULLM, p, off);
    if (lane == 0) out[(size_t)4 * N_NODES] = p + b3[0];
}

// ---------------------------------------------------------------- launch
extern "C" void kernel_launch(void* const* d_in, const int* in_sizes, int n_in,
                              void* d_out, int out_size)
{
    const float* x    = (const float*)d_in[0];
    const int*   ei   = (const int*)  d_in[1];
    const float* aW   = (const float*)d_in[2];
    const float* ab   = (const float*)d_in[3];
    const float* aW1  = (const float*)d_in[4];
    const float* ab1  = (const float*)d_in[5];
    const float* aW2  = (const float*)d_in[6];
    const float* ab2  = (const float*)d_in[7];
    const float* aW3  = (const float*)d_in[8];
    const float* ab3  = (const float*)d_in[9];
    const float* cW   = (const float*)d_in[10];
    const float* cb   = (const float*)d_in[11];
    const float* cW1  = (const float*)d_in[12];
    const float* cb1  = (const float*)d_in[13];
    const float* cW2  = (const float*)d_in[14];
    const float* cb2  = (const float*)d_in[15];
    const float* cW3  = (const float*)d_in[16];
    const float* cb3  = (const float*)d_in[17];
    float* out = (float*)d_out;

    const int* src = ei;
    const int* dst = ei + N_EDGES;

    k_init  <<<(N_NODES + 255) / 256, 256>>>();
    k_degree<<<(N_EDGES + 255) / 256, 256>>>(dst);
    k_dinv  <<<(N_NODES + 255) / 256, 256>>>();
    k_scan1 <<<SCAN_G, SCAN_B>>>();
    k_scan2 <<<1, 128>>>();
    k_scan3 <<<SCAN_G, SCAN_B>>>();
    k_fill  <<<(N_EDGES + 255) / 256, 256>>>(src, dst);

    dim3 ggrid((N_NODES + 127) / 128, 2);
    k_gemm<<<ggrid, 256>>>(x, aW, cW);

    k_aggregate<<<2048, 256>>>(x, ab, cb, aW1, ab1, aW2, ab2, aW3, ab3, out);

    k_value<<<1, 32>>>(cW1, cb1, cW2, cb2, cW3, cb3, out);
}

// round 6
// speedup vs baseline: 2.0894x; 1.1391x over previous
#include <cuda_runtime.h>
#include <cuda_fp16.h>
#include <math.h>

#define N_NODES 100000
#define N_EDGES 1600000
#define CCH 128
#define C2  256
#define FULLM 0xffffffffu
#define SCAN_B 1024
#define SCAN_G ((N_NODES + SCAN_B - 1) / SCAN_B)   // 98
#define GEMM_BX ((N_NODES + 127) / 128)            // 782
#define FILL_B  ((N_EDGES + 255) / 256)            // 6250

// ---------------- device scratch (no allocation allowed) ----------------
// fp16 feature table: per node 32 lanes x 16B; lane l = {actor ch 4l..4l+3, critic ch 4l..4l+3}
__device__ uint4 g_feat_h[(size_t)N_NODES * 32];
__device__ int   g_deg [N_NODES];                // deg incl. self loop
__device__ float g_dinv[N_NODES];
__device__ int   g_off [N_NODES + 1];            // CSR offsets (in-edges only)
__device__ int   g_cur [N_NODES];                // fill cursors
__device__ int   g_csr [N_EDGES];                // src per dst-sorted edge
__device__ int   g_bsum[SCAN_G];                 // per-block sums for scan
__device__ float g_csum[CCH];                    // critic graph readout

__device__ __forceinline__ unsigned int h2_as_u32(__half2 h) {
    return *reinterpret_cast<unsigned int*>(&h);
}

// ---------------------------------------------------------------- init
__global__ void k_init() {
    int i = blockIdx.x * blockDim.x + threadIdx.x;
    if (i < N_NODES) g_deg[i] = 1;          // self loop
    if (i < CCH)     g_csum[i] = 0.f;
}

__global__ void k_degree(const int* __restrict__ dst) {
    int i = blockIdx.x * blockDim.x + threadIdx.x;
    if (i < N_EDGES) atomicAdd(&g_deg[dst[i]], 1);
}

__global__ void k_dinv() {
    int i = blockIdx.x * blockDim.x + threadIdx.x;
    if (i < N_NODES) g_dinv[i] = rsqrtf((float)g_deg[i]);
}

// ---------------- 3-phase parallel exclusive scan of (deg-1) ----------------
__device__ __forceinline__ int block_excl_scan(int v, int lane, int wid, int* warp_sums, int nwarp) {
    int inc = v;
#pragma unroll
    for (int o = 1; o < 32; o <<= 1) {
        int u = __shfl_up_sync(FULLM, inc, o);
        if (lane >= o) inc += u;
    }
    if (lane == 31) warp_sums[wid] = inc;
    __syncthreads();
    if (wid == 0) {
        int w = (lane < nwarp) ? warp_sums[lane] : 0;
#pragma unroll
        for (int o = 1; o < 32; o <<= 1) {
            int u = __shfl_up_sync(FULLM, w, o);
            if (lane >= o) w += u;
        }
        warp_sums[lane] = w;
    }
    __syncthreads();
    return (inc - v) + (wid ? warp_sums[wid - 1] : 0);
}

__global__ void k_scan1() {
    __shared__ int warp_sums[32];
    int i = blockIdx.x * SCAN_B + threadIdx.x;
    int d = (i < N_NODES) ? (g_deg[i] - 1) : 0;
    int ex = block_excl_scan(d, threadIdx.x & 31, threadIdx.x >> 5, warp_sums, SCAN_B / 32);
    if (i < N_NODES) g_off[i] = ex;
    if (threadIdx.x == SCAN_B - 1) g_bsum[blockIdx.x] = ex + d;
}

__global__ void k_scan2() {
    __shared__ int warp_sums[32];
    int t = threadIdx.x;                    // 128 threads >= SCAN_G
    int v = (t < SCAN_G) ? g_bsum[t] : 0;
    int ex = block_excl_scan(v, t & 31, t >> 5, warp_sums, 4);
    if (t < SCAN_G) g_bsum[t] = ex;
}

__global__ void k_scan3() {
    int i = blockIdx.x * SCAN_B + threadIdx.x;
    if (i < N_NODES) {
        int o = g_off[i] + g_bsum[blockIdx.x];
        g_off[i] = o;
        g_cur[i] = o;
    }
    if (i == 0) g_off[N_NODES] = N_EDGES;   // sum of (deg-1) == E analytically
}

// ---------------------------------------------------------------- f32x2 helpers
__device__ __forceinline__ unsigned long long pack2(float x, float y) {
    unsigned long long r;
    asm("mov.b64 %0, {%1, %2};" : "=l"(r) : "f"(x), "f"(y));
    return r;
}
__device__ __forceinline__ void fma2(unsigned long long& d,
                                     unsigned long long a, unsigned long long b) {
    asm("fma.rn.f32x2 %0, %1, %2, %0;" : "+l"(d) : "l"(a), "l"(b));
}
__device__ __forceinline__ float2 unpack2(unsigned long long v) {
    float2 f;
    asm("mov.b64 {%0, %1}, %2;" : "=f"(f.x), "=f"(f.y) : "l"(v));
    return f;
}

// ---------------------------------------------------------------- fused GEMM + CSR fill
// Blocks [0, 2*GEMM_BX): h[N,256] = x[N,128] @ [Wa|Wc], store fp16 * dinv.
// Blocks [2*GEMM_BX, +FILL_B): CSR fill (independent work, overlapped).
__global__ __launch_bounds__(256, 2)
void k_gemm_fill(const float* __restrict__ x,
                 const float* __restrict__ Wa,
                 const float* __restrict__ Wc,
                 const int* __restrict__ src,
                 const int* __restrict__ dst)
{
    if (blockIdx.x >= 2 * GEMM_BX) {
        int e = (blockIdx.x - 2 * GEMM_BX) * 256 + threadIdx.x;
        if (e < N_EDGES) {
            int d = dst[e];
            int p = atomicAdd(&g_cur[d], 1);
            g_csr[p] = src[e];
        }
        return;
    }

    __shared__ float As[16][128];
    __shared__ float Bs[16][128];

    const int half = (blockIdx.x >= GEMM_BX) ? 1 : 0;    // 0 = actor, 1 = critic
    const int bm   = (blockIdx.x - half * GEMM_BX) * 128;
    const float* W = half ? Wc : Wa;
    const int tid  = threadIdx.x;
    const int tx   = tid & 15, ty = tid >> 4;

    const int lr = tid >> 2;                     // 0..63
    const int lk = (tid & 3) * 4;                // 0,4,8,12
    const int br = tid >> 4;                     // 0..15
    const int bc = (tid & 15) * 8;               // 0..120

    unsigned long long acc[8][4];
#pragma unroll
    for (int i = 0; i < 8; i++)
#pragma unroll
        for (int j = 0; j < 4; j++) acc[i][j] = 0ull;

    for (int k0 = 0; k0 < CCH; k0 += 16) {
#pragma unroll
        for (int h = 0; h < 128; h += 64) {
            int row = bm + lr + h;
            float4 v = make_float4(0.f, 0.f, 0.f, 0.f);
            if (row < N_NODES)
                v = *reinterpret_cast<const float4*>(&x[(size_t)row * CCH + k0 + lk]);
            As[lk + 0][lr + h] = v.x; As[lk + 1][lr + h] = v.y;
            As[lk + 2][lr + h] = v.z; As[lk + 3][lr + h] = v.w;
        }
        *reinterpret_cast<float4*>(&Bs[br][bc]) =
            *reinterpret_cast<const float4*>(&W[(size_t)(k0 + br) * CCH + bc]);
        *reinterpret_cast<float4*>(&Bs[br][bc + 4]) =
            *reinterpret_cast<const float4*>(&W[(size_t)(k0 + br) * CCH + bc + 4]);
        __syncthreads();

#pragma unroll
        for (int kk = 0; kk < 16; kk++) {
            float4 a0 = *reinterpret_cast<const float4*>(&As[kk][ty * 8]);
            float4 a1 = *reinterpret_cast<const float4*>(&As[kk][ty * 8 + 4]);
            float4 b0 = *reinterpret_cast<const float4*>(&Bs[kk][tx * 8]);
            float4 b1 = *reinterpret_cast<const float4*>(&Bs[kk][tx * 8 + 4]);
            unsigned long long bp[4];
            bp[0] = pack2(b0.x, b0.y); bp[1] = pack2(b0.z, b0.w);
            bp[2] = pack2(b1.x, b1.y); bp[3] = pack2(b1.z, b1.w);
            float av[8] = {a0.x, a0.y, a0.z, a0.w, a1.x, a1.y, a1.z, a1.w};
#pragma unroll
            for (int i = 0; i < 8; i++) {
                unsigned long long ap = pack2(av[i], av[i]);
#pragma unroll
                for (int j = 0; j < 4; j++) fma2(acc[i][j], ap, bp[j]);
            }
        }
        __syncthreads();
    }

    // store fp16, interleaved layout: uint2 index = (row*32 + lane)*2 + half
    uint2* fh = reinterpret_cast<uint2*>(g_feat_h);
    const int row0 = bm + ty * 8;
#pragma unroll
    for (int i = 0; i < 8; i++) {
        int row = row0 + i;
        if (row >= N_NODES) continue;
        float dv = g_dinv[row];
        float2 r0 = unpack2(acc[i][0]), r1 = unpack2(acc[i][1]);
        float2 r2 = unpack2(acc[i][2]), r3 = unpack2(acc[i][3]);
        __half2 h0 = __floats2half2_rn(r0.x * dv, r0.y * dv);
        __half2 h1 = __floats2half2_rn(r1.x * dv, r1.y * dv);
        __half2 h2 = __floats2half2_rn(r2.x * dv, r2.y * dv);
        __half2 h3 = __floats2half2_rn(r3.x * dv, r3.y * dv);
        // channels 8tx..8tx+3 -> lane 2tx ; channels 8tx+4..8tx+7 -> lane 2tx+1
        uint2 u0, u1;
        u0.x = h2_as_u32(h0); u0.y = h2_as_u32(h1);
        u1.x = h2_as_u32(h2); u1.y = h2_as_u32(h3);
        size_t base = ((size_t)row * 32 + 2 * tx) * 2 + half;
        fh[base]     = u0;
        fh[base + 2] = u1;
    }
}

// ---------------------------------------------------------------- fused gather + epilogue
__device__ __forceinline__ float softplus_f(float v) {
    return fmaxf(v, 0.f) + log1pf(expf(-fabsf(v))) + 1e-20f;
}

__device__ __forceinline__ void addh(float4& A, float4& Cc, uint4 v) {
    float2 f0 = __half22float2(*reinterpret_cast<__half2*>(&v.x));
    float2 f1 = __half22float2(*reinterpret_cast<__half2*>(&v.y));
    float2 f2 = __half22float2(*reinterpret_cast<__half2*>(&v.z));
    float2 f3 = __half22float2(*reinterpret_cast<__half2*>(&v.w));
    A.x += f0.x; A.y += f0.y; A.z += f1.x; A.w += f1.y;
    Cc.x += f2.x; Cc.y += f2.y; Cc.z += f3.x; Cc.w += f3.y;
}

__global__ void k_aggregate(const float* __restrict__ x,
                            const float* __restrict__ a_conv_b,
                            const float* __restrict__ c_conv_b,
                            const float* __restrict__ W1, const float* __restrict__ b1,
                            const float* __restrict__ W2, const float* __restrict__ b2,
                            const float* __restrict__ W3, const float* __restrict__ b3,
                            float* __restrict__ out)
{
    __shared__ float sW1[CCH * 32];
    __shared__ float sW2[32 * 32];
    __shared__ float sW3[32 * 4];
    __shared__ float sb1[32], sb2[32], sb3[4];
    __shared__ float sab[CCH], scb[CCH];
    __shared__ float scsum[CCH];

    const int tid = threadIdx.x;
    for (int i = tid; i < CCH * 32; i += blockDim.x) sW1[i] = W1[i];
    for (int i = tid; i < 32 * 32;  i += blockDim.x) sW2[i] = W2[i];
    if (tid < 128) { sW3[tid] = W3[tid]; sab[tid] = a_conv_b[tid];
                     scb[tid] = c_conv_b[tid]; scsum[tid] = 0.f; }
    if (tid < 32)  { sb1[tid] = b1[tid]; sb2[tid] = b2[tid]; }
    if (tid < 4)   { sb3[tid] = b3[tid]; }
    __syncthreads();

    const int lane = tid & 31;
    const int warp = tid >> 5;
    const int gw = blockIdx.x * (blockDim.x >> 5) + warp;
    const int nw = gridDim.x * (blockDim.x >> 5);

    float4 cs = make_float4(0.f, 0.f, 0.f, 0.f);

    for (int node = gw; node < N_NODES; node += nw) {
        const float dv = g_dinv[node];
        float4 A  = make_float4(0.f, 0.f, 0.f, 0.f);
        float4 Cc = make_float4(0.f, 0.f, 0.f, 0.f);
        addh(A, Cc, g_feat_h[(size_t)node * 32 + lane]);     // self loop

        const int beg = g_off[node], end = g_off[node + 1];
        int j = beg;
        for (; j + 1 < end; j += 2) {
            int s0 = g_csr[j], s1 = g_csr[j + 1];
            uint4 v0 = g_feat_h[(size_t)s0 * 32 + lane];
            uint4 v1 = g_feat_h[(size_t)s1 * 32 + lane];
            addh(A, Cc, v0);
            addh(A, Cc, v1);
        }
        if (j < end) {
            uint4 v0 = g_feat_h[(size_t)g_csr[j] * 32 + lane];
            addh(A, Cc, v0);
        }

        float4 xv = reinterpret_cast<const float4*>(x)[(size_t)node * 32 + lane];
        int c0 = 4 * lane;
        float4 a;
        a.x = fmaxf(fmaf(A.x, dv, sab[c0 + 0]), 0.f) + xv.x;
        a.y = fmaxf(fmaf(A.y, dv, sab[c0 + 1]), 0.f) + xv.y;
        a.z = fmaxf(fmaf(A.z, dv, sab[c0 + 2]), 0.f) + xv.z;
        a.w = fmaxf(fmaf(A.w, dv, sab[c0 + 3]), 0.f) + xv.w;

        cs.x += fmaxf(fmaf(Cc.x, dv, scb[c0 + 0]), 0.f) + xv.x;
        cs.y += fmaxf(fmaf(Cc.y, dv, scb[c0 + 1]), 0.f) + xv.y;
        cs.z += fmaxf(fmaf(Cc.z, dv, scb[c0 + 2]), 0.f) + xv.z;
        cs.w += fmaxf(fmaf(Cc.w, dv, scb[c0 + 3]), 0.f) + xv.w;

        float h1 = sb1[lane];
#pragma unroll
        for (int r = 0; r < 32; r++) {
            float axr = __shfl_sync(FULLM, a.x, r);
            float ayr = __shfl_sync(FULLM, a.y, r);
            float azr = __shfl_sync(FULLM, a.z, r);
            float awr = __shfl_sync(FULLM, a.w, r);
            h1 = fmaf(axr, sW1[(4 * r + 0) * 32 + lane], h1);
            h1 = fmaf(ayr, sW1[(4 * r + 1) * 32 + lane], h1);
            h1 = fmaf(azr, sW1[(4 * r + 2) * 32 + lane], h1);
            h1 = fmaf(awr, sW1[(4 * r + 3) * 32 + lane], h1);
        }
        h1 = fmaxf(h1, 0.f);

        float h2 = sb2[lane];
#pragma unroll
        for (int r = 0; r < 32; r++)
            h2 = fmaf(__shfl_sync(FULLM, h1, r), sW2[r * 32 + lane], h2);
        h2 = fmaxf(h2, 0.f);

        float o = (lane < 4) ? sb3[lane] : 0.f;
#pragma unroll
        for (int r = 0; r < 32; r++) {
            float hv = __shfl_sync(FULLM, h2, r);
            if (lane < 4) o = fmaf(hv, sW3[r * 4 + lane], o);
        }

        if (lane < 4) {
            float sp = softplus_f(o);
            if (lane == 0) out[node] = sp;
            else           out[N_NODES + (size_t)node * 3 + (lane - 1)] = sp;
        }
    }

    int c0 = 4 * lane;
    atomicAdd(&scsum[c0 + 0], cs.x);
    atomicAdd(&scsum[c0 + 1], cs.y);
    atomicAdd(&scsum[c0 + 2], cs.z);
    atomicAdd(&scsum[c0 + 3], cs.w);
    __syncthreads();
    if (tid < CCH) atomicAdd(&g_csum[tid], scsum[tid]);
}

// ---------------------------------------------------------------- critic head
__global__ void k_value(const float* __restrict__ W1, const float* __restrict__ b1,
                        const float* __restrict__ W2, const float* __restrict__ b2,
                        const float* __restrict__ W3, const float* __restrict__ b3,
                        float* __restrict__ out)
{
    const int lane = threadIdx.x;   // 32 threads
    float c0 = g_csum[lane], c1 = g_csum[lane + 32],
          c2 = g_csum[lane + 64], c3 = g_csum[lane + 96];

    float h1 = b1[lane];
#pragma unroll
    for (int r = 0; r < 32; r++)
        h1 = fmaf(__shfl_sync(FULLM, c0, r), W1[(r      ) * 32 + lane], h1);
#pragma unroll
    for (int r = 0; r < 32; r++)
        h1 = fmaf(__shfl_sync(FULLM, c1, r), W1[(r + 32 ) * 32 + lane], h1);
#pragma unroll
    for (int r = 0; r < 32; r++)
        h1 = fmaf(__shfl_sync(FULLM, c2, r), W1[(r + 64 ) * 32 + lane], h1);
#pragma unroll
    for (int r = 0; r < 32; r++)
        h1 = fmaf(__shfl_sync(FULLM, c3, r), W1[(r + 96 ) * 32 + lane], h1);
    h1 = fmaxf(h1, 0.f);

    float h2 = b2[lane];
#pragma unroll
    for (int r = 0; r < 32; r++)
        h2 = fmaf(__shfl_sync(FULLM, h1, r), W2[r * 32 + lane], h2);
    h2 = fmaxf(h2, 0.f);

    float p = h2 * W3[lane];
#pragma unroll
    for (int off = 16; off > 0; off >>= 1)
        p += __shfl_xor_sync(FULLM, p, off);
    if (lane == 0) out[(size_t)4 * N_NODES] = p + b3[0];
}

// ---------------------------------------------------------------- launch
extern "C" void kernel_launch(void* const* d_in, const int* in_sizes, int n_in,
                              void* d_out, int out_size)
{
    const float* x    = (const float*)d_in[0];
    const int*   ei   = (const int*)  d_in[1];
    const float* aW   = (const float*)d_in[2];
    const float* ab   = (const float*)d_in[3];
    const float* aW1  = (const float*)d_in[4];
    const float* ab1  = (const float*)d_in[5];
    const float* aW2  = (const float*)d_in[6];
    const float* ab2  = (const float*)d_in[7];
    const float* aW3  = (const float*)d_in[8];
    const float* ab3  = (const float*)d_in[9];
    const float* cW   = (const float*)d_in[10];
    const float* cb   = (const float*)d_in[11];
    const float* cW1  = (const float*)d_in[12];
    const float* cb1  = (const float*)d_in[13];
    const float* cW2  = (const float*)d_in[14];
    const float* cb2  = (const float*)d_in[15];
    const float* cW3  = (const float*)d_in[16];
    const float* cb3  = (const float*)d_in[17];
    float* out = (float*)d_out;

    const int* src = ei;
    const int* dst = ei + N_EDGES;

    k_init  <<<(N_NODES + 255) / 256, 256>>>();
    k_degree<<<(N_EDGES + 255) / 256, 256>>>(dst);
    k_dinv  <<<(N_NODES + 255) / 256, 256>>>();
    k_scan1 <<<SCAN_G, SCAN_B>>>();
    k_scan2 <<<1, 128>>>();
    k_scan3 <<<SCAN_G, SCAN_B>>>();

    k_gemm_fill<<<2 * GEMM_BX + FILL_B, 256>>>(x, aW, cW, src, dst);

    k_aggregate<<<2048, 256>>>(x, ab, cb, aW1, ab1, aW2, ab2, aW3, ab3, out);

    k_value<<<1, 32>>>(cW1, cb1, cW2, cb2, cW3, cb3, out);
}

// round 9
// speedup vs baseline: 2.4795x; 1.1867x over previous
#include <cuda_runtime.h>
#include <cuda_fp16.h>
#include <cuda_bf16.h>
#include <stdint.h>
#include <math.h>

#define N_NODES 100000
#define N_EDGES 1600000
#define CCH 128
#define FULLM 0xffffffffu
#define SCAN_B 1024
#define SCAN_G ((N_NODES + SCAN_B - 1) / SCAN_B)   // 98
#define GEMM_BX ((N_NODES + 127) / 128)            // 782
#define FILL_B  ((N_EDGES + 255) / 256)            // 6250

// ---------------- device scratch (no allocation allowed) ----------------
__device__ uint4 g_feat_h[(size_t)N_NODES * 32];   // fp16 table: lane l = {actor 4l..4l+3, critic 4l..4l+3}
__device__ int   g_deg [N_NODES];
__device__ float g_dinv[N_NODES];
__device__ int   g_off [N_NODES + 1];
__device__ int   g_cur [N_NODES];
__device__ int   g_csr [N_EDGES];
__device__ int   g_bsum[SCAN_G];
__device__ float g_csum[CCH];
__device__ unsigned short g_wt_hi[2 * CCH * CCH];  // W^T bf16 hi: [half][n][k]
__device__ unsigned short g_wt_lo[2 * CCH * CCH];  // W^T bf16 lo residual

__device__ __forceinline__ unsigned int h2_as_u32(__half2 h) {
    return *reinterpret_cast<unsigned int*>(&h);
}

// ---------------------------------------------------------------- init / degree / dinv
__global__ void k_init() {
    int i = blockIdx.x * blockDim.x + threadIdx.x;
    if (i < N_NODES) g_deg[i] = 1;
    if (i < CCH)     g_csum[i] = 0.f;
}
__global__ void k_degree(const int* __restrict__ dst) {
    int i = blockIdx.x * blockDim.x + threadIdx.x;
    if (i < N_EDGES) atomicAdd(&g_deg[dst[i]], 1);
}
__global__ void k_dinv() {
    int i = blockIdx.x * blockDim.x + threadIdx.x;
    if (i < N_NODES) g_dinv[i] = rsqrtf((float)g_deg[i]);
}

// ---------------- 3-phase parallel exclusive scan of (deg-1) ----------------
__device__ __forceinline__ int block_excl_scan(int v, int lane, int wid, int* warp_sums, int nwarp) {
    int inc = v;
#pragma unroll
    for (int o = 1; o < 32; o <<= 1) {
        int u = __shfl_up_sync(FULLM, inc, o);
        if (lane >= o) inc += u;
    }
    if (lane == 31) warp_sums[wid] = inc;
    __syncthreads();
    if (wid == 0) {
        int w = (lane < nwarp) ? warp_sums[lane] : 0;
#pragma unroll
        for (int o = 1; o < 32; o <<= 1) {
            int u = __shfl_up_sync(FULLM, w, o);
            if (lane >= o) w += u;
        }
        warp_sums[lane] = w;
    }
    __syncthreads();
    return (inc - v) + (wid ? warp_sums[wid - 1] : 0);
}
__global__ void k_scan1() {
    __shared__ int warp_sums[32];
    int i = blockIdx.x * SCAN_B + threadIdx.x;
    int d = (i < N_NODES) ? (g_deg[i] - 1) : 0;
    int ex = block_excl_scan(d, threadIdx.x & 31, threadIdx.x >> 5, warp_sums, SCAN_B / 32);
    if (i < N_NODES) g_off[i] = ex;
    if (threadIdx.x == SCAN_B - 1) g_bsum[blockIdx.x] = ex + d;
}
__global__ void k_scan2() {
    __shared__ int warp_sums[32];
    int t = threadIdx.x;
    int v = (t < SCAN_G) ? g_bsum[t] : 0;
    int ex = block_excl_scan(v, t & 31, t >> 5, warp_sums, 4);
    if (t < SCAN_G) g_bsum[t] = ex;
}
__global__ void k_scan3() {
    int i = blockIdx.x * SCAN_B + threadIdx.x;
    if (i < N_NODES) {
        int o = g_off[i] + g_bsum[blockIdx.x];
        g_off[i] = o;
        g_cur[i] = o;
    }
    if (i == 0) g_off[N_NODES] = N_EDGES;
}

// ---------------------------------------------------------------- W^T bf16 split prep
__global__ void k_wprep(const float* __restrict__ Wa, const float* __restrict__ Wc) {
    int idx = blockIdx.x * blockDim.x + threadIdx.x;
    if (idx >= 2 * CCH * CCH) return;
    int h = idx >> 14;
    int rem = idx & 16383;
    int n = rem >> 7, k = rem & 127;
    const float* W = h ? Wc : Wa;
    float w = W[k * CCH + n];
    __nv_bfloat16 hi = __float2bfloat16(w);
    float r = w - __bfloat162float(hi);
    __nv_bfloat16 lo = __float2bfloat16(r);
    g_wt_hi[idx] = *reinterpret_cast<unsigned short*>(&hi);
    g_wt_lo[idx] = *reinterpret_cast<unsigned short*>(&lo);
}

// ---------------------------------------------------------------- mma.sync GEMM + CSR fill
// Blocks [0, 2*GEMM_BX): 128x128 tile via m16n8k16 bf16 HMMA, split-precision
// (Ahi*Bhi + Ahi*Blo + Alo*Bhi), fp32 accum. Store fp16*dinv table.
// Blocks [2*GEMM_BX, +FILL_B): CSR fill.
#define KC 64                       // k-chunk
#define LDAB 72                     // smem row stride in bf16 (144 B, conflict-free)
#define SM_AHI 0
#define SM_ALO (SM_AHI + 128 * LDAB * 2)
#define SM_BHI (SM_ALO + 128 * LDAB * 2)
#define SM_BLO (SM_BHI + 128 * LDAB * 2)
#define SM_TOTAL_MMA (SM_BLO + 128 * LDAB * 2)    // 73728 B

__device__ __forceinline__ void mma16816(float c[4], const uint32_t a[4], const uint32_t b[2]) {
    asm volatile("mma.sync.aligned.m16n8k16.row.col.f32.bf16.bf16.f32 "
                 "{%0,%1,%2,%3}, {%4,%5,%6,%7}, {%8,%9}, {%0,%1,%2,%3};\n"
                 : "+f"(c[0]), "+f"(c[1]), "+f"(c[2]), "+f"(c[3])
                 : "r"(a[0]), "r"(a[1]), "r"(a[2]), "r"(a[3]), "r"(b[0]), "r"(b[1]));
}

__global__ __launch_bounds__(256)
void k_gemm_fill(const float* __restrict__ x,
                 const int* __restrict__ src,
                 const int* __restrict__ dst)
{
    if (blockIdx.x >= 2 * GEMM_BX) {
        int e = (blockIdx.x - 2 * GEMM_BX) * 256 + threadIdx.x;
        if (e < N_EDGES) {
            int d = dst[e];
            int p = atomicAdd(&g_cur[d], 1);
            g_csr[p] = src[e];
        }
        return;
    }

    extern __shared__ char smem[];
    const int tid  = threadIdx.x;
    const int wid  = tid >> 5, lane = tid & 31;
    const int half = (blockIdx.x >= GEMM_BX) ? 1 : 0;
    const int bm   = (blockIdx.x - half * GEMM_BX) * 128;
    const int wm   = wid & 3;        // warp row group (32 rows)
    const int wn   = wid >> 2;       // warp col group (64 cols)
    const int lq   = lane >> 2;      // 0..7
    const int lr   = lane & 3;       // 0..3

    float acc[2][8][4];
#pragma unroll
    for (int i = 0; i < 2; i++)
#pragma unroll
        for (int j = 0; j < 8; j++)
#pragma unroll
            for (int q = 0; q < 4; q++) acc[i][j][q] = 0.f;

    for (int kc = 0; kc < CCH; kc += KC) {
        // ---- load A (x rows, bf16 hi/lo split) ----
        for (int g = tid; g < 1024; g += 256) {
            int row = g >> 3, c8 = (g & 7) * 8;
            float f[8];
            if (bm + row < N_NODES) {
                const float4* xp = reinterpret_cast<const float4*>(
                    &x[(size_t)(bm + row) * CCH + kc + c8]);
                float4 v0 = xp[0], v1 = xp[1];
                f[0] = v0.x; f[1] = v0.y; f[2] = v0.z; f[3] = v0.w;
                f[4] = v1.x; f[5] = v1.y; f[6] = v1.z; f[7] = v1.w;
            } else {
#pragma unroll
                for (int i = 0; i < 8; i++) f[i] = 0.f;
            }
            unsigned short hs[8], ls[8];
#pragma unroll
            for (int i = 0; i < 8; i++) {
                __nv_bfloat16 h = __float2bfloat16(f[i]);
                float r = f[i] - __bfloat162float(h);
                __nv_bfloat16 l = __float2bfloat16(r);
                hs[i] = *reinterpret_cast<unsigned short*>(&h);
                ls[i] = *reinterpret_cast<unsigned short*>(&l);
            }
            uint32_t off = row * (LDAB * 2) + c8 * 2;
            *reinterpret_cast<uint4*>(smem + SM_AHI + off) =
                make_uint4(hs[0] | ((uint32_t)hs[1] << 16), hs[2] | ((uint32_t)hs[3] << 16),
                           hs[4] | ((uint32_t)hs[5] << 16), hs[6] | ((uint32_t)hs[7] << 16));
            *reinterpret_cast<uint4*>(smem + SM_ALO + off) =
                make_uint4(ls[0] | ((uint32_t)ls[1] << 16), ls[2] | ((uint32_t)ls[3] << 16),
                           ls[4] | ((uint32_t)ls[5] << 16), ls[6] | ((uint32_t)ls[7] << 16));
        }
        // ---- load B (precomputed W^T bf16) ----
        for (int g = tid; g < 1024; g += 256) {
            int n = g >> 3, c8 = (g & 7) * 8;
            size_t ei = ((size_t)(half * 128 + n)) * 128 + kc + c8;
            uint32_t off = n * (LDAB * 2) + c8 * 2;
            *reinterpret_cast<uint4*>(smem + SM_BHI + off) =
                *reinterpret_cast<const uint4*>(&g_wt_hi[ei]);
            *reinterpret_cast<uint4*>(smem + SM_BLO + off) =
                *reinterpret_cast<const uint4*>(&g_wt_lo[ei]);
        }
        __syncthreads();

#pragma unroll
        for (int ks = 0; ks < KC / 16; ks++) {
            const int k16 = ks * 16;
            uint32_t ah[2][4], al[2][4];
#pragma unroll
            for (int ma = 0; ma < 2; ma++) {
                int r0 = wm * 32 + ma * 16 + lq;
                int c0 = k16 + lr * 2;
                uint32_t o00 = r0 * (LDAB * 2) + c0 * 2;
                uint32_t o10 = o00 + 8 * (LDAB * 2);
                ah[ma][0] = *reinterpret_cast<uint32_t*>(smem + SM_AHI + o00);
                ah[ma][1] = *reinterpret_cast<uint32_t*>(smem + SM_AHI + o10);
                ah[ma][2] = *reinterpret_cast<uint32_t*>(smem + SM_AHI + o00 + 16);
                ah[ma][3] = *reinterpret_cast<uint32_t*>(smem + SM_AHI + o10 + 16);
                al[ma][0] = *reinterpret_cast<uint32_t*>(smem + SM_ALO + o00);
                al[ma][1] = *reinterpret_cast<uint32_t*>(smem + SM_ALO + o10);
                al[ma][2] = *reinterpret_cast<uint32_t*>(smem + SM_ALO + o00 + 16);
                al[ma][3] = *reinterpret_cast<uint32_t*>(smem + SM_ALO + o10 + 16);
            }
            uint32_t bh[8][2], bl[8][2];
#pragma unroll
            for (int nb = 0; nb < 8; nb++) {
                int n = wn * 64 + nb * 8 + lq;
                int k0 = k16 + lr * 2;
                uint32_t o0 = n * (LDAB * 2) + k0 * 2;
                bh[nb][0] = *reinterpret_cast<uint32_t*>(smem + SM_BHI + o0);
                bh[nb][1] = *reinterpret_cast<uint32_t*>(smem + SM_BHI + o0 + 16);
                bl[nb][0] = *reinterpret_cast<uint32_t*>(smem + SM_BLO + o0);
                bl[nb][1] = *reinterpret_cast<uint32_t*>(smem + SM_BLO + o0 + 16);
            }
#pragma unroll
            for (int ma = 0; ma < 2; ma++)
#pragma unroll
                for (int nb = 0; nb < 8; nb++) {
                    mma16816(acc[ma][nb], ah[ma], bh[nb]);
                    mma16816(acc[ma][nb], ah[ma], bl[nb]);
                    mma16816(acc[ma][nb], al[ma], bh[nb]);
                }
        }
        __syncthreads();
    }

    // ---- epilogue: scale by dinv[row], convert fp16, store table ----
    unsigned char* fb = reinterpret_cast<unsigned char*>(g_feat_h);
#pragma unroll
    for (int ma = 0; ma < 2; ma++) {
        int row0 = bm + wm * 32 + ma * 16 + lq;      // rows row0, row0+8
        int row1 = row0 + 8;
        float dv0 = (row0 < N_NODES) ? g_dinv[row0] : 0.f;
        float dv1 = (row1 < N_NODES) ? g_dinv[row1] : 0.f;
#pragma unroll
        for (int nb = 0; nb < 8; nb++) {
            int cpair = wn * 32 + nb * 4 + lr;
            uint32_t cb = (uint32_t)(cpair >> 1) * 16 + (uint32_t)half * 8 + (cpair & 1) * 4;
            if (row0 < N_NODES) {
                *reinterpret_cast<uint32_t*>(fb + (size_t)row0 * 512 + cb) =
                    h2_as_u32(__floats2half2_rn(acc[ma][nb][0] * dv0, acc[ma][nb][1] * dv0));
            }
            if (row1 < N_NODES) {
                *reinterpret_cast<uint32_t*>(fb + (size_t)row1 * 512 + cb) =
                    h2_as_u32(__floats2half2_rn(acc[ma][nb][2] * dv1, acc[ma][nb][3] * dv1));
            }
        }
    }
}

// ---------------------------------------------------------------- fused gather + epilogue
__device__ __forceinline__ float softplus_f(float v) {
    return fmaxf(v, 0.f) + log1pf(expf(-fabsf(v))) + 1e-20f;
}
__device__ __forceinline__ void addh(float4& A, float4& Cc, uint4 v) {
    float2 f0 = __half22float2(*reinterpret_cast<__half2*>(&v.x));
    float2 f1 = __half22float2(*reinterpret_cast<__half2*>(&v.y));
    float2 f2 = __half22float2(*reinterpret_cast<__half2*>(&v.z));
    float2 f3 = __half22float2(*reinterpret_cast<__half2*>(&v.w));
    A.x += f0.x; A.y += f0.y; A.z += f1.x; A.w += f1.y;
    Cc.x += f2.x; Cc.y += f2.y; Cc.z += f3.x; Cc.w += f3.y;
}

__global__ void k_aggregate(const float* __restrict__ x,
                            const float* __restrict__ a_conv_b,
                            const float* __restrict__ c_conv_b,
                            const float* __restrict__ W1, const float* __restrict__ b1,
                            const float* __restrict__ W2, const float* __restrict__ b2,
                            const float* __restrict__ W3, const float* __restrict__ b3,
                            float* __restrict__ out)
{
    __shared__ float sW1[CCH * 32];
    __shared__ float sW2[32 * 32];
    __shared__ float sW3[32 * 4];
    __shared__ float sb1[32], sb2[32], sb3[4];
    __shared__ float sab[CCH], scb[CCH];
    __shared__ float scsum[CCH];

    const int tid = threadIdx.x;
    for (int i = tid; i < CCH * 32; i += blockDim.x) sW1[i] = W1[i];
    for (int i = tid; i < 32 * 32;  i += blockDim.x) sW2[i] = W2[i];
    if (tid < 128) { sW3[tid] = W3[tid]; sab[tid] = a_conv_b[tid];
                     scb[tid] = c_conv_b[tid]; scsum[tid] = 0.f; }
    if (tid < 32)  { sb1[tid] = b1[tid]; sb2[tid] = b2[tid]; }
    if (tid < 4)   { sb3[tid] = b3[tid]; }
    __syncthreads();

    const int lane = tid & 31;
    const int warp = tid >> 5;
    const int gw = blockIdx.x * (blockDim.x >> 5) + warp;
    const int nw = gridDim.x * (blockDim.x >> 5);

    float4 cs = make_float4(0.f, 0.f, 0.f, 0.f);

    for (int node = gw; node < N_NODES; node += nw) {
        const float dv = g_dinv[node];
        float4 A  = make_float4(0.f, 0.f, 0.f, 0.f);
        float4 Cc = make_float4(0.f, 0.f, 0.f, 0.f);
        addh(A, Cc, g_feat_h[(size_t)node * 32 + lane]);     // self loop

        const int beg = g_off[node], end = g_off[node + 1];
        int j = beg;
        for (; j + 3 < end; j += 4) {
            int s0 = g_csr[j], s1 = g_csr[j + 1], s2 = g_csr[j + 2], s3 = g_csr[j + 3];
            uint4 v0 = g_feat_h[(size_t)s0 * 32 + lane];
            uint4 v1 = g_feat_h[(size_t)s1 * 32 + lane];
            uint4 v2 = g_feat_h[(size_t)s2 * 32 + lane];
            uint4 v3 = g_feat_h[(size_t)s3 * 32 + lane];
            addh(A, Cc, v0); addh(A, Cc, v1); addh(A, Cc, v2); addh(A, Cc, v3);
        }
        for (; j < end; j++) {
            uint4 v0 = g_feat_h[(size_t)g_csr[j] * 32 + lane];
            addh(A, Cc, v0);
        }

        float4 xv = reinterpret_cast<const float4*>(x)[(size_t)node * 32 + lane];
        int c0 = 4 * lane;
        float4 a;
        a.x = fmaxf(fmaf(A.x, dv, sab[c0 + 0]), 0.f) + xv.x;
        a.y = fmaxf(fmaf(A.y, dv, sab[c0 + 1]), 0.f) + xv.y;
        a.z = fmaxf(fmaf(A.z, dv, sab[c0 + 2]), 0.f) + xv.z;
        a.w = fmaxf(fmaf(A.w, dv, sab[c0 + 3]), 0.f) + xv.w;

        cs.x += fmaxf(fmaf(Cc.x, dv, scb[c0 + 0]), 0.f) + xv.x;
        cs.y += fmaxf(fmaf(Cc.y, dv, scb[c0 + 1]), 0.f) + xv.y;
        cs.z += fmaxf(fmaf(Cc.z, dv, scb[c0 + 2]), 0.f) + xv.z;
        cs.w += fmaxf(fmaf(Cc.w, dv, scb[c0 + 3]), 0.f) + xv.w;

        float h1 = sb1[lane];
#pragma unroll
        for (int r = 0; r < 32; r++) {
            float axr = __shfl_sync(FULLM, a.x, r);
            float ayr = __shfl_sync(FULLM, a.y, r);
            float azr = __shfl_sync(FULLM, a.z, r);
            float awr = __shfl_sync(FULLM, a.w, r);
            h1 = fmaf(axr, sW1[(4 * r + 0) * 32 + lane], h1);
            h1 = fmaf(ayr, sW1[(4 * r + 1) * 32 + lane], h1);
            h1 = fmaf(azr, sW1[(4 * r + 2) * 32 + lane], h1);
            h1 = fmaf(awr, sW1[(4 * r + 3) * 32 + lane], h1);
        }
        h1 = fmaxf(h1, 0.f);

        float h2 = sb2[lane];
#pragma unroll
        for (int r = 0; r < 32; r++)
            h2 = fmaf(__shfl_sync(FULLM, h1, r), sW2[r * 32 + lane], h2);
        h2 = fmaxf(h2, 0.f);

        float o = (lane < 4) ? sb3[lane] : 0.f;
#pragma unroll
        for (int r = 0; r < 32; r++) {
            float hv = __shfl_sync(FULLM, h2, r);
            if (lane < 4) o = fmaf(hv, sW3[r * 4 + lane], o);
        }

        if (lane < 4) {
            float sp = softplus_f(o);
            if (lane == 0) out[node] = sp;
            else           out[N_NODES + (size_t)node * 3 + (lane - 1)] = sp;
        }
    }

    int c0 = 4 * lane;
    atomicAdd(&scsum[c0 + 0], cs.x);
    atomicAdd(&scsum[c0 + 1], cs.y);
    atomicAdd(&scsum[c0 + 2], cs.z);
    atomicAdd(&scsum[c0 + 3], cs.w);
    __syncthreads();
    if (tid < CCH) atomicAdd(&g_csum[tid], scsum[tid]);
}

// ---------------------------------------------------------------- critic head
__global__ void k_value(const float* __restrict__ W1, const float* __restrict__ b1,
                        const float* __restrict__ W2, const float* __restrict__ b2,
                        const float* __restrict__ W3, const float* __restrict__ b3,
                        float* __restrict__ out)
{
    const int lane = threadIdx.x;
    float c0 = g_csum[lane], c1 = g_csum[lane + 32],
          c2 = g_csum[lane + 64], c3 = g_csum[lane + 96];

    float h1 = b1[lane];
#pragma unroll
    for (int r = 0; r < 32; r++)
        h1 = fmaf(__shfl_sync(FULLM, c0, r), W1[(r      ) * 32 + lane], h1);
#pragma unroll
    for (int r = 0; r < 32; r++)
        h1 = fmaf(__shfl_sync(FULLM, c1, r), W1[(r + 32 ) * 32 + lane], h1);
#pragma unroll
    for (int r = 0; r < 32; r++)
        h1 = fmaf(__shfl_sync(FULLM, c2, r), W1[(r + 64 ) * 32 + lane], h1);
#pragma unroll
    for (int r = 0; r < 32; r++)
        h1 = fmaf(__shfl_sync(FULLM, c3, r), W1[(r + 96 ) * 32 + lane], h1);
    h1 = fmaxf(h1, 0.f);

    float h2 = b2[lane];
#pragma unroll
    for (int r = 0; r < 32; r++)
        h2 = fmaf(__shfl_sync(FULLM, h1, r), W2[r * 32 + lane], h2);
    h2 = fmaxf(h2, 0.f);

    float p = h2 * W3[lane];
#pragma unroll
    for (int off = 16; off > 0; off >>= 1)
        p += __shfl_xor_sync(FULLM, p, off);
    if (lane == 0) out[(size_t)4 * N_NODES] = p + b3[0];
}

// ---------------------------------------------------------------- launch
extern "C" void kernel_launch(void* const* d_in, const int* in_sizes, int n_in,
                              void* d_out, int out_size)
{
    const float* x    = (const float*)d_in[0];
    const int*   ei   = (const int*)  d_in[1];
    const float* aW   = (const float*)d_in[2];
    const float* ab   = (const float*)d_in[3];
    const float* aW1  = (const float*)d_in[4];
    const float* ab1  = (const float*)d_in[5];
    const float* aW2  = (const float*)d_in[6];
    const float* ab2  = (const float*)d_in[7];
    const float* aW3  = (const float*)d_in[8];
    const float* ab3  = (const float*)d_in[9];
    const float* cW   = (const float*)d_in[10];
    const float* cb   = (const float*)d_in[11];
    const float* cW1  = (const float*)d_in[12];
    const float* cb1  = (const float*)d_in[13];
    const float* cW2  = (const float*)d_in[14];
    const float* cb2  = (const float*)d_in[15];
    const float* cW3  = (const float*)d_in[16];
    const float* cb3  = (const float*)d_in[17];
    float* out = (float*)d_out;

    const int* src = ei;
    const int* dst = ei + N_EDGES;

    cudaFuncSetAttribute((const void*)k_gemm_fill,
                         cudaFuncAttributeMaxDynamicSharedMemorySize, SM_TOTAL_MMA);

    k_init  <<<(N_NODES + 255) / 256, 256>>>();
    k_wprep <<<(2 * CCH * CCH + 255) / 256, 256>>>(aW, cW);
    k_degree<<<(N_EDGES + 255) / 256, 256>>>(dst);
    k_dinv  <<<(N_NODES + 255) / 256, 256>>>();
    k_scan1 <<<SCAN_G, SCAN_B>>>();
    k_scan2 <<<1, 128>>>();
    k_scan3 <<<SCAN_G, SCAN_B>>>();

    k_gemm_fill<<<2 * GEMM_BX + FILL_B, 256, SM_TOTAL_MMA>>>(x, src, dst);

    k_aggregate<<<2048, 256>>>(x, ab, cb, aW1, ab1, aW2, ab2, aW3, ab3, out);

    k_value<<<1, 32>>>(cW1, cb1, cW2, cb2, cW3, cb3, out);
}

// round 10
// speedup vs baseline: 3.0695x; 1.2380x over previous
#include <cuda_runtime.h>
#include <cuda_fp16.h>
#include <cuda_bf16.h>
#include <stdint.h>
#include <math.h>

#define N_NODES 100000
#define N_EDGES 1600000
#define CCH 128
#define FULLM 0xffffffffu
#define SCAN_B 1024
#define SCAN_G ((N_NODES + SCAN_B - 1) / SCAN_B)   // 98
#define GEMM_BX ((N_NODES + 127) / 128)            // 782
#define FILL_B  ((N_EDGES + 255) / 256)            // 6250

// ---------------- device scratch (no allocation allowed) ----------------
__device__ uint4 g_feat_h[(size_t)N_NODES * 32];   // fp16 table: lane l = {actor 4l..4l+3, critic 4l..4l+3}
__device__ uint4 g_atab[(size_t)N_NODES * 16];     // fp16 actor activations a[N,128]
__device__ int   g_deg [N_NODES];
__device__ float g_dinv[N_NODES];
__device__ int   g_off [N_NODES + 1];
__device__ int   g_cur [N_NODES];
__device__ int   g_csr [N_EDGES];
__device__ int   g_bsum[SCAN_G];
__device__ float g_csum[CCH];
__device__ unsigned short g_wt_hi[2 * CCH * CCH];  // W^T bf16 hi: [half][n][k]
__device__ unsigned short g_wt_lo[2 * CCH * CCH];  // W^T bf16 lo residual
__device__ unsigned short g_w1t[32 * 128];         // W1^T fp16 [n][k]
__device__ unsigned short g_w2t[32 * 32];          // W2^T fp16 [n][k]
__device__ unsigned short g_w3t[8 * 32];           // W3^T fp16 [n][k], rows 4..7 zero

__device__ __forceinline__ unsigned int h2_as_u32(__half2 h) {
    return *reinterpret_cast<unsigned int*>(&h);
}

// ---------------------------------------------------------------- init / degree / dinv
__global__ void k_init() {
    int i = blockIdx.x * blockDim.x + threadIdx.x;
    if (i < N_NODES) g_deg[i] = 1;
    if (i < CCH)     g_csum[i] = 0.f;
}
__global__ void k_degree(const int* __restrict__ dst) {
    int i = blockIdx.x * blockDim.x + threadIdx.x;
    if (i < N_EDGES) atomicAdd(&g_deg[dst[i]], 1);
}
__global__ void k_dinv() {
    int i = blockIdx.x * blockDim.x + threadIdx.x;
    if (i < N_NODES) g_dinv[i] = rsqrtf((float)g_deg[i]);
}

// ---------------- 3-phase parallel exclusive scan of (deg-1) ----------------
__device__ __forceinline__ int block_excl_scan(int v, int lane, int wid, int* warp_sums, int nwarp) {
    int inc = v;
#pragma unroll
    for (int o = 1; o < 32; o <<= 1) {
        int u = __shfl_up_sync(FULLM, inc, o);
        if (lane >= o) inc += u;
    }
    if (lane == 31) warp_sums[wid] = inc;
    __syncthreads();
    if (wid == 0) {
        int w = (lane < nwarp) ? warp_sums[lane] : 0;
#pragma unroll
        for (int o = 1; o < 32; o <<= 1) {
            int u = __shfl_up_sync(FULLM, w, o);
            if (lane >= o) w += u;
        }
        warp_sums[lane] = w;
    }
    __syncthreads();
    return (inc - v) + (wid ? warp_sums[wid - 1] : 0);
}
__global__ void k_scan1() {
    __shared__ int warp_sums[32];
    int i = blockIdx.x * SCAN_B + threadIdx.x;
    int d = (i < N_NODES) ? (g_deg[i] - 1) : 0;
    int ex = block_excl_scan(d, threadIdx.x & 31, threadIdx.x >> 5, warp_sums, SCAN_B / 32);
    if (i < N_NODES) g_off[i] = ex;
    if (threadIdx.x == SCAN_B - 1) g_bsum[blockIdx.x] = ex + d;
}
__global__ void k_scan2() {
    __shared__ int warp_sums[32];
    int t = threadIdx.x;
    int v = (t < SCAN_G) ? g_bsum[t] : 0;
    int ex = block_excl_scan(v, t & 31, t >> 5, warp_sums, 4);
    if (t < SCAN_G) g_bsum[t] = ex;
}
__global__ void k_scan3() {
    int i = blockIdx.x * SCAN_B + threadIdx.x;
    if (i < N_NODES) {
        int o = g_off[i] + g_bsum[blockIdx.x];
        g_off[i] = o;
        g_cur[i] = o;
    }
    if (i == 0) g_off[N_NODES] = N_EDGES;
}

// ---------------------------------------------------------------- weight preps
__global__ void k_wprep(const float* __restrict__ Wa, const float* __restrict__ Wc) {
    int idx = blockIdx.x * blockDim.x + threadIdx.x;
    if (idx >= 2 * CCH * CCH) return;
    int h = idx >> 14;
    int rem = idx & 16383;
    int n = rem >> 7, k = rem & 127;
    const float* W = h ? Wc : Wa;
    float w = W[k * CCH + n];
    __nv_bfloat16 hi = __float2bfloat16(w);
    float r = w - __bfloat162float(hi);
    __nv_bfloat16 lo = __float2bfloat16(r);
    g_wt_hi[idx] = *reinterpret_cast<unsigned short*>(&hi);
    g_wt_lo[idx] = *reinterpret_cast<unsigned short*>(&lo);
}
__global__ void k_mlpprep(const float* __restrict__ W1, const float* __restrict__ W2,
                          const float* __restrict__ W3) {
    int idx = blockIdx.x * blockDim.x + threadIdx.x;
    if (idx < 32 * 128) {
        int n = idx >> 7, k = idx & 127;
        __half h = __float2half(W1[k * 32 + n]);
        g_w1t[idx] = *reinterpret_cast<unsigned short*>(&h);
    } else if (idx < 32 * 128 + 32 * 32) {
        int j = idx - 32 * 128;
        int n = j >> 5, k = j & 31;
        __half h = __float2half(W2[k * 32 + n]);
        g_w2t[j] = *reinterpret_cast<unsigned short*>(&h);
    } else if (idx < 32 * 128 + 32 * 32 + 8 * 32) {
        int j = idx - 32 * 128 - 32 * 32;
        int n = j >> 5, k = j & 31;
        float v = (n < 4) ? W3[k * 4 + n] : 0.f;
        __half h = __float2half(v);
        g_w3t[j] = *reinterpret_cast<unsigned short*>(&h);
    }
}

// ---------------------------------------------------------------- mma.sync GEMM + CSR fill
#define KC 64
#define LDAB 72
#define SM_AHI 0
#define SM_ALO (SM_AHI + 128 * LDAB * 2)
#define SM_BHI (SM_ALO + 128 * LDAB * 2)
#define SM_BLO (SM_BHI + 128 * LDAB * 2)
#define SM_TOTAL_MMA (SM_BLO + 128 * LDAB * 2)    // 73728 B

__device__ __forceinline__ void mma16816(float c[4], const uint32_t a[4], const uint32_t b[2]) {
    asm volatile("mma.sync.aligned.m16n8k16.row.col.f32.bf16.bf16.f32 "
                 "{%0,%1,%2,%3}, {%4,%5,%6,%7}, {%8,%9}, {%0,%1,%2,%3};\n"
                 : "+f"(c[0]), "+f"(c[1]), "+f"(c[2]), "+f"(c[3])
                 : "r"(a[0]), "r"(a[1]), "r"(a[2]), "r"(a[3]), "r"(b[0]), "r"(b[1]));
}
__device__ __forceinline__ void mma16816h(float c[4], const uint32_t a[4], const uint32_t b[2]) {
    asm volatile("mma.sync.aligned.m16n8k16.row.col.f32.f16.f16.f32 "
                 "{%0,%1,%2,%3}, {%4,%5,%6,%7}, {%8,%9}, {%0,%1,%2,%3};\n"
                 : "+f"(c[0]), "+f"(c[1]), "+f"(c[2]), "+f"(c[3])
                 : "r"(a[0]), "r"(a[1]), "r"(a[2]), "r"(a[3]), "r"(b[0]), "r"(b[1]));
}

__global__ __launch_bounds__(256)
void k_gemm_fill(const float* __restrict__ x,
                 const int* __restrict__ src,
                 const int* __restrict__ dst)
{
    if (blockIdx.x >= 2 * GEMM_BX) {
        int e = (blockIdx.x - 2 * GEMM_BX) * 256 + threadIdx.x;
        if (e < N_EDGES) {
            int d = dst[e];
            int p = atomicAdd(&g_cur[d], 1);
            g_csr[p] = src[e];
        }
        return;
    }

    extern __shared__ char smem[];
    const int tid  = threadIdx.x;
    const int wid  = tid >> 5, lane = tid & 31;
    const int half = (blockIdx.x >= GEMM_BX) ? 1 : 0;
    const int bm   = (blockIdx.x - half * GEMM_BX) * 128;
    const int wm   = wid & 3;
    const int wn   = wid >> 2;
    const int lq   = lane >> 2;
    const int lr   = lane & 3;

    float acc[2][8][4];
#pragma unroll
    for (int i = 0; i < 2; i++)
#pragma unroll
        for (int j = 0; j < 8; j++)
#pragma unroll
            for (int q = 0; q < 4; q++) acc[i][j][q] = 0.f;

    for (int kc = 0; kc < CCH; kc += KC) {
        for (int g = tid; g < 1024; g += 256) {
            int row = g >> 3, c8 = (g & 7) * 8;
            float f[8];
            if (bm + row < N_NODES) {
                const float4* xp = reinterpret_cast<const float4*>(
                    &x[(size_t)(bm + row) * CCH + kc + c8]);
                float4 v0 = xp[0], v1 = xp[1];
                f[0] = v0.x; f[1] = v0.y; f[2] = v0.z; f[3] = v0.w;
                f[4] = v1.x; f[5] = v1.y; f[6] = v1.z; f[7] = v1.w;
            } else {
#pragma unroll
                for (int i = 0; i < 8; i++) f[i] = 0.f;
            }
            unsigned short hs[8], ls[8];
#pragma unroll
            for (int i = 0; i < 8; i++) {
                __nv_bfloat16 h = __float2bfloat16(f[i]);
                float r = f[i] - __bfloat162float(h);
                __nv_bfloat16 l = __float2bfloat16(r);
                hs[i] = *reinterpret_cast<unsigned short*>(&h);
                ls[i] = *reinterpret_cast<unsigned short*>(&l);
            }
            uint32_t off = row * (LDAB * 2) + c8 * 2;
            *reinterpret_cast<uint4*>(smem + SM_AHI + off) =
                make_uint4(hs[0] | ((uint32_t)hs[1] << 16), hs[2] | ((uint32_t)hs[3] << 16),
                           hs[4] | ((uint32_t)hs[5] << 16), hs[6] | ((uint32_t)hs[7] << 16));
            *reinterpret_cast<uint4*>(smem + SM_ALO + off) =
                make_uint4(ls[0] | ((uint32_t)ls[1] << 16), ls[2] | ((uint32_t)ls[3] << 16),
                           ls[4] | ((uint32_t)ls[5] << 16), ls[6] | ((uint32_t)ls[7] << 16));
        }
        for (int g = tid; g < 1024; g += 256) {
            int n = g >> 3, c8 = (g & 7) * 8;
            size_t ei = ((size_t)(half * 128 + n)) * 128 + kc + c8;
            uint32_t off = n * (LDAB * 2) + c8 * 2;
            *reinterpret_cast<uint4*>(smem + SM_BHI + off) =
                *reinterpret_cast<const uint4*>(&g_wt_hi[ei]);
            *reinterpret_cast<uint4*>(smem + SM_BLO + off) =
                *reinterpret_cast<const uint4*>(&g_wt_lo[ei]);
        }
        __syncthreads();

#pragma unroll
        for (int ks = 0; ks < KC / 16; ks++) {
            const int k16 = ks * 16;
            uint32_t ah[2][4], al[2][4];
#pragma unroll
            for (int ma = 0; ma < 2; ma++) {
                int r0 = wm * 32 + ma * 16 + lq;
                int c0 = k16 + lr * 2;
                uint32_t o00 = r0 * (LDAB * 2) + c0 * 2;
                uint32_t o10 = o00 + 8 * (LDAB * 2);
                ah[ma][0] = *reinterpret_cast<uint32_t*>(smem + SM_AHI + o00);
                ah[ma][1] = *reinterpret_cast<uint32_t*>(smem + SM_AHI + o10);
                ah[ma][2] = *reinterpret_cast<uint32_t*>(smem + SM_AHI + o00 + 16);
                ah[ma][3] = *reinterpret_cast<uint32_t*>(smem + SM_AHI + o10 + 16);
                al[ma][0] = *reinterpret_cast<uint32_t*>(smem + SM_ALO + o00);
                al[ma][1] = *reinterpret_cast<uint32_t*>(smem + SM_ALO + o10);
                al[ma][2] = *reinterpret_cast<uint32_t*>(smem + SM_ALO + o00 + 16);
                al[ma][3] = *reinterpret_cast<uint32_t*>(smem + SM_ALO + o10 + 16);
            }
            uint32_t bh[8][2], bl[8][2];
#pragma unroll
            for (int nb = 0; nb < 8; nb++) {
                int n = wn * 64 + nb * 8 + lq;
                int k0 = k16 + lr * 2;
                uint32_t o0 = n * (LDAB * 2) + k0 * 2;
                bh[nb][0] = *reinterpret_cast<uint32_t*>(smem + SM_BHI + o0);
                bh[nb][1] = *reinterpret_cast<uint32_t*>(smem + SM_BHI + o0 + 16);
                bl[nb][0] = *reinterpret_cast<uint32_t*>(smem + SM_BLO + o0);
                bl[nb][1] = *reinterpret_cast<uint32_t*>(smem + SM_BLO + o0 + 16);
            }
#pragma unroll
            for (int ma = 0; ma < 2; ma++)
#pragma unroll
                for (int nb = 0; nb < 8; nb++) {
                    mma16816(acc[ma][nb], ah[ma], bh[nb]);
                    mma16816(acc[ma][nb], ah[ma], bl[nb]);
                    mma16816(acc[ma][nb], al[ma], bh[nb]);
                }
        }
        __syncthreads();
    }

    unsigned char* fb = reinterpret_cast<unsigned char*>(g_feat_h);
#pragma unroll
    for (int ma = 0; ma < 2; ma++) {
        int row0 = bm + wm * 32 + ma * 16 + lq;
        int row1 = row0 + 8;
        float dv0 = (row0 < N_NODES) ? g_dinv[row0] : 0.f;
        float dv1 = (row1 < N_NODES) ? g_dinv[row1] : 0.f;
#pragma unroll
        for (int nb = 0; nb < 8; nb++) {
            int cpair = wn * 32 + nb * 4 + lr;
            uint32_t cb = (uint32_t)(cpair >> 1) * 16 + (uint32_t)half * 8 + (cpair & 1) * 4;
            if (row0 < N_NODES) {
                *reinterpret_cast<uint32_t*>(fb + (size_t)row0 * 512 + cb) =
                    h2_as_u32(__floats2half2_rn(acc[ma][nb][0] * dv0, acc[ma][nb][1] * dv0));
            }
            if (row1 < N_NODES) {
                *reinterpret_cast<uint32_t*>(fb + (size_t)row1 * 512 + cb) =
                    h2_as_u32(__floats2half2_rn(acc[ma][nb][2] * dv1, acc[ma][nb][3] * dv1));
            }
        }
    }
}

// ---------------------------------------------------------------- gather + conv epilogue
__device__ __forceinline__ void addh(float4& A, float4& Cc, uint4 v) {
    float2 f0 = __half22float2(*reinterpret_cast<__half2*>(&v.x));
    float2 f1 = __half22float2(*reinterpret_cast<__half2*>(&v.y));
    float2 f2 = __half22float2(*reinterpret_cast<__half2*>(&v.z));
    float2 f3 = __half22float2(*reinterpret_cast<__half2*>(&v.w));
    A.x += f0.x; A.y += f0.y; A.z += f1.x; A.w += f1.y;
    Cc.x += f2.x; Cc.y += f2.y; Cc.z += f3.x; Cc.w += f3.y;
}

__global__ void k_aggregate(const float* __restrict__ x,
                            const float* __restrict__ a_conv_b,
                            const float* __restrict__ c_conv_b)
{
    __shared__ float sab[CCH], scb[CCH];
    __shared__ float scsum[CCH];

    const int tid = threadIdx.x;
    if (tid < 128) { sab[tid] = a_conv_b[tid]; scb[tid] = c_conv_b[tid]; scsum[tid] = 0.f; }
    __syncthreads();

    const int lane = tid & 31;
    const int warp = tid >> 5;
    const int gw = blockIdx.x * (blockDim.x >> 5) + warp;
    const int nw = gridDim.x * (blockDim.x >> 5);

    float4 cs = make_float4(0.f, 0.f, 0.f, 0.f);
    uint2* atab = reinterpret_cast<uint2*>(g_atab);

    for (int node = gw; node < N_NODES; node += nw) {
        const float dv = g_dinv[node];
        float4 A  = make_float4(0.f, 0.f, 0.f, 0.f);
        float4 Cc = make_float4(0.f, 0.f, 0.f, 0.f);
        addh(A, Cc, g_feat_h[(size_t)node * 32 + lane]);     // self loop

        const int beg = g_off[node], end = g_off[node + 1];
        int j = beg;
        for (; j + 3 < end; j += 4) {
            int s0 = g_csr[j], s1 = g_csr[j + 1], s2 = g_csr[j + 2], s3 = g_csr[j + 3];
            uint4 v0 = g_feat_h[(size_t)s0 * 32 + lane];
            uint4 v1 = g_feat_h[(size_t)s1 * 32 + lane];
            uint4 v2 = g_feat_h[(size_t)s2 * 32 + lane];
            uint4 v3 = g_feat_h[(size_t)s3 * 32 + lane];
            addh(A, Cc, v0); addh(A, Cc, v1); addh(A, Cc, v2); addh(A, Cc, v3);
        }
        for (; j < end; j++) {
            uint4 v0 = g_feat_h[(size_t)g_csr[j] * 32 + lane];
            addh(A, Cc, v0);
        }

        float4 xv = reinterpret_cast<const float4*>(x)[(size_t)node * 32 + lane];
        int c0 = 4 * lane;
        float4 a;
        a.x = fmaxf(fmaf(A.x, dv, sab[c0 + 0]), 0.f) + xv.x;
        a.y = fmaxf(fmaf(A.y, dv, sab[c0 + 1]), 0.f) + xv.y;
        a.z = fmaxf(fmaf(A.z, dv, sab[c0 + 2]), 0.f) + xv.z;
        a.w = fmaxf(fmaf(A.w, dv, sab[c0 + 3]), 0.f) + xv.w;

        uint2 av;
        av.x = h2_as_u32(__floats2half2_rn(a.x, a.y));
        av.y = h2_as_u32(__floats2half2_rn(a.z, a.w));
        atab[(size_t)node * 32 + lane] = av;

        cs.x += fmaxf(fmaf(Cc.x, dv, scb[c0 + 0]), 0.f) + xv.x;
        cs.y += fmaxf(fmaf(Cc.y, dv, scb[c0 + 1]), 0.f) + xv.y;
        cs.z += fmaxf(fmaf(Cc.z, dv, scb[c0 + 2]), 0.f) + xv.z;
        cs.w += fmaxf(fmaf(Cc.w, dv, scb[c0 + 3]), 0.f) + xv.w;
    }

    int c0 = 4 * lane;
    atomicAdd(&scsum[c0 + 0], cs.x);
    atomicAdd(&scsum[c0 + 1], cs.y);
    atomicAdd(&scsum[c0 + 2], cs.z);
    atomicAdd(&scsum[c0 + 3], cs.w);
    __syncthreads();
    if (tid < CCH) atomicAdd(&g_csum[tid], scsum[tid]);
}

// ---------------------------------------------------------------- actor MLP via mma.sync
// Block: 128 nodes, 128 threads (4 warps, warp w = 32 nodes). fp16 acts, fp32 accum.
#define MLP_LDA 136    // halves, stride of A rows
#define MLP_LDH 40     // halves, stride of H rows
#define OFF_A  0                     // 128*136*2 = 34816
#define OFF_H1 34816                 // 128*40*2 = 10240
#define OFF_H2 45056                 // 10240
#define OFF_W1 55296                 // 32*136*2 = 8704
#define OFF_W2 64000                 // 32*40*2 = 2560
#define OFF_W3 66560                 // 8*40*2 = 640
#define OFF_B  67200                 // 32+32+4 floats = 272
#define MLP_SMEM 67584

__device__ __forceinline__ float softplus_f(float v) {
    return fmaxf(v, 0.f) + log1pf(expf(-fabsf(v))) + 1e-20f;
}

__global__ __launch_bounds__(128)
void k_mlp(const float* __restrict__ b1, const float* __restrict__ b2,
           const float* __restrict__ b3, float* __restrict__ out)
{
    extern __shared__ char sm[];
    const int tid = threadIdx.x;
    const int w = tid >> 5, lane = tid & 31;
    const int lq = lane >> 2, lr = lane & 3;
    const int bm = blockIdx.x * 128;

    float* fb1 = reinterpret_cast<float*>(sm + OFF_B);
    float* fb2 = fb1 + 32;
    float* fb3 = fb2 + 32;

    // stage weights/biases
    for (int g = tid; g < 32 * 64; g += 128) {
        int n = g >> 6, k2 = g & 63;
        *reinterpret_cast<uint32_t*>(sm + OFF_W1 + n * (MLP_LDA * 2) + k2 * 4) =
            reinterpret_cast<const uint32_t*>(g_w1t)[n * 64 + k2];
    }
    for (int g = tid; g < 32 * 16; g += 128) {
        int n = g >> 4, k2 = g & 15;
        *reinterpret_cast<uint32_t*>(sm + OFF_W2 + n * (MLP_LDH * 2) + k2 * 4) =
            reinterpret_cast<const uint32_t*>(g_w2t)[n * 16 + k2];
    }
    if (tid < 128) {
        int n = tid >> 4, k2 = tid & 15;
        *reinterpret_cast<uint32_t*>(sm + OFF_W3 + n * (MLP_LDH * 2) + k2 * 4) =
            reinterpret_cast<const uint32_t*>(g_w3t)[n * 16 + k2];
    }
    if (tid < 32) { fb1[tid] = b1[tid]; fb2[tid] = b2[tid]; }
    if (tid < 4)  { fb3[tid] = b3[tid]; }
    // stage A tile (128 nodes x 128 ch fp16)
    for (int g = tid; g < 128 * 16; g += 128) {
        int row = g >> 4, q = g & 15;
        uint4 v = make_uint4(0u, 0u, 0u, 0u);
        if (bm + row < N_NODES) v = g_atab[(size_t)(bm + row) * 16 + q];
        *reinterpret_cast<uint4*>(sm + OFF_A + row * (MLP_LDA * 2) + q * 16) = v;
    }
    __syncthreads();

    // ---- layer 1: [32 x 128] @ [128 x 32] ----
    float acc1[2][4][4];
#pragma unroll
    for (int i = 0; i < 2; i++)
#pragma unroll
        for (int j = 0; j < 4; j++)
#pragma unroll
            for (int q = 0; q < 4; q++) acc1[i][j][q] = 0.f;

#pragma unroll
    for (int ks = 0; ks < 8; ks++) {
        uint32_t a[2][4];
#pragma unroll
        for (int ma = 0; ma < 2; ma++) {
            int row = w * 32 + ma * 16 + lq;
            uint32_t o = OFF_A + row * (MLP_LDA * 2) + (ks * 16 + lr * 2) * 2;
            a[ma][0] = *reinterpret_cast<uint32_t*>(sm + o);
            a[ma][1] = *reinterpret_cast<uint32_t*>(sm + o + 8 * (MLP_LDA * 2));
            a[ma][2] = *reinterpret_cast<uint32_t*>(sm + o + 16);
            a[ma][3] = *reinterpret_cast<uint32_t*>(sm + o + 8 * (MLP_LDA * 2) + 16);
        }
#pragma unroll
        for (int nb = 0; nb < 4; nb++) {
            int n = nb * 8 + lq;
            uint32_t o = OFF_W1 + n * (MLP_LDA * 2) + (ks * 16 + lr * 2) * 2;
            uint32_t b[2];
            b[0] = *reinterpret_cast<uint32_t*>(sm + o);
            b[1] = *reinterpret_cast<uint32_t*>(sm + o + 16);
#pragma unroll
            for (int ma = 0; ma < 2; ma++) mma16816h(acc1[ma][nb], a[ma], b);
        }
    }
    // bias + relu -> sH1 fp16
#pragma unroll
    for (int ma = 0; ma < 2; ma++) {
        int row = w * 32 + ma * 16 + lq;
#pragma unroll
        for (int nb = 0; nb < 4; nb++) {
            int col = nb * 8 + lr * 2;
            float v0 = fmaxf(acc1[ma][nb][0] + fb1[col], 0.f);
            float v1 = fmaxf(acc1[ma][nb][1] + fb1[col + 1], 0.f);
            float v2 = fmaxf(acc1[ma][nb][2] + fb1[col], 0.f);
            float v3 = fmaxf(acc1[ma][nb][3] + fb1[col + 1], 0.f);
            *reinterpret_cast<uint32_t*>(sm + OFF_H1 + row * (MLP_LDH * 2) + col * 2) =
                h2_as_u32(__floats2half2_rn(v0, v1));
            *reinterpret_cast<uint32_t*>(sm + OFF_H1 + (row + 8) * (MLP_LDH * 2) + col * 2) =
                h2_as_u32(__floats2half2_rn(v2, v3));
        }
    }
    __syncwarp();

    // ---- layer 2: [32 x 32] @ [32 x 32] ----
    float acc2[2][4][4];
#pragma unroll
    for (int i = 0; i < 2; i++)
#pragma unroll
        for (int j = 0; j < 4; j++)
#pragma unroll
            for (int q = 0; q < 4; q++) acc2[i][j][q] = 0.f;
#pragma unroll
    for (int ks = 0; ks < 2; ks++) {
        uint32_t a[2][4];
#pragma unroll
        for (int ma = 0; ma < 2; ma++) {
            int row = w * 32 + ma * 16 + lq;
            uint32_t o = OFF_H1 + row * (MLP_LDH * 2) + (ks * 16 + lr * 2) * 2;
            a[ma][0] = *reinterpret_cast<uint32_t*>(sm + o);
            a[ma][1] = *reinterpret_cast<uint32_t*>(sm + o + 8 * (MLP_LDH * 2));
            a[ma][2] = *reinterpret_cast<uint32_t*>(sm + o + 16);
            a[ma][3] = *reinterpret_cast<uint32_t*>(sm + o + 8 * (MLP_LDH * 2) + 16);
        }
#pragma unroll
        for (int nb = 0; nb < 4; nb++) {
            int n = nb * 8 + lq;
            uint32_t o = OFF_W2 + n * (MLP_LDH * 2) + (ks * 16 + lr * 2) * 2;
            uint32_t b[2];
            b[0] = *reinterpret_cast<uint32_t*>(sm + o);
            b[1] = *reinterpret_cast<uint32_t*>(sm + o + 16);
#pragma unroll
            for (int ma = 0; ma < 2; ma++) mma16816h(acc2[ma][nb], a[ma], b);
        }
    }
#pragma unroll
    for (int ma = 0; ma < 2; ma++) {
        int row = w * 32 + ma * 16 + lq;
#pragma unroll
        for (int nb = 0; nb < 4; nb++) {
            int col = nb * 8 + lr * 2;
            float v0 = fmaxf(acc2[ma][nb][0] + fb2[col], 0.f);
            float v1 = fmaxf(acc2[ma][nb][1] + fb2[col + 1], 0.f);
            float v2 = fmaxf(acc2[ma][nb][2] + fb2[col], 0.f);
            float v3 = fmaxf(acc2[ma][nb][3] + fb2[col + 1], 0.f);
            *reinterpret_cast<uint32_t*>(sm + OFF_H2 + row * (MLP_LDH * 2) + col * 2) =
                h2_as_u32(__floats2half2_rn(v0, v1));
            *reinterpret_cast<uint32_t*>(sm + OFF_H2 + (row + 8) * (MLP_LDH * 2) + col * 2) =
                h2_as_u32(__floats2half2_rn(v2, v3));
        }
    }
    __syncwarp();

    // ---- layer 3: [32 x 32] @ [32 x 8] (cols 4..7 zero) ----
    float acc3[2][4];
#pragma unroll
    for (int i = 0; i < 2; i++)
#pragma unroll
        for (int q = 0; q < 4; q++) acc3[i][q] = 0.f;
#pragma unroll
    for (int ks = 0; ks < 2; ks++) {
        uint32_t a[2][4];
#pragma unroll
        for (int ma = 0; ma < 2; ma++) {
            int row = w * 32 + ma * 16 + lq;
            uint32_t o = OFF_H2 + row * (MLP_LDH * 2) + (ks * 16 + lr * 2) * 2;
            a[ma][0] = *reinterpret_cast<uint32_t*>(sm + o);
            a[ma][1] = *reinterpret_cast<uint32_t*>(sm + o + 8 * (MLP_LDH * 2));
            a[ma][2] = *reinterpret_cast<uint32_t*>(sm + o + 16);
            a[ma][3] = *reinterpret_cast<uint32_t*>(sm + o + 8 * (MLP_LDH * 2) + 16);
        }
        int n = lq;
        uint32_t o = OFF_W3 + n * (MLP_LDH * 2) + (ks * 16 + lr * 2) * 2;
        uint32_t b[2];
        b[0] = *reinterpret_cast<uint32_t*>(sm + o);
        b[1] = *reinterpret_cast<uint32_t*>(sm + o + 16);
#pragma unroll
        for (int ma = 0; ma < 2; ma++) mma16816h(acc3[ma], a[ma], b);
    }
    // outputs: cols 2lr, 2lr+1 (valid when < 4)
    if (lr < 2) {
        int ca = 2 * lr, cb = 2 * lr + 1;
#pragma unroll
        for (int ma = 0; ma < 2; ma++) {
            int r0 = bm + w * 32 + ma * 16 + lq;
            int r1 = r0 + 8;
            if (r0 < N_NODES) {
                float s0 = softplus_f(acc3[ma][0] + fb3[ca]);
                float s1 = softplus_f(acc3[ma][1] + fb3[cb]);
                if (ca == 0) out[r0] = s0; else out[N_NODES + (size_t)r0 * 3 + ca - 1] = s0;
                out[N_NODES + (size_t)r0 * 3 + cb - 1] = s1;
            }
            if (r1 < N_NODES) {
                float s2 = softplus_f(acc3[ma][2] + fb3[ca]);
                float s3 = softplus_f(acc3[ma][3] + fb3[cb]);
                if (ca == 0) out[r1] = s2; else out[N_NODES + (size_t)r1 * 3 + ca - 1] = s2;
                out[N_NODES + (size_t)r1 * 3 + cb - 1] = s3;
            }
        }
    }
}

// ---------------------------------------------------------------- critic head
__global__ void k_value(const float* __restrict__ W1, const float* __restrict__ b1,
                        const float* __restrict__ W2, const float* __restrict__ b2,
                        const float* __restrict__ W3, const float* __restrict__ b3,
                        float* __restrict__ out)
{
    const int lane = threadIdx.x;
    float c0 = g_csum[lane], c1 = g_csum[lane + 32],
          c2 = g_csum[lane + 64], c3 = g_csum[lane + 96];

    float h1 = b1[lane];
#pragma unroll
    for (int r = 0; r < 32; r++)
        h1 = fmaf(__shfl_sync(FULLM, c0, r), W1[(r      ) * 32 + lane], h1);
#pragma unroll
    for (int r = 0; r < 32; r++)
        h1 = fmaf(__shfl_sync(FULLM, c1, r), W1[(r + 32 ) * 32 + lane], h1);
#pragma unroll
    for (int r = 0; r < 32; r++)
        h1 = fmaf(__shfl_sync(FULLM, c2, r), W1[(r + 64 ) * 32 + lane], h1);
#pragma unroll
    for (int r = 0; r < 32; r++)
        h1 = fmaf(__shfl_sync(FULLM, c3, r), W1[(r + 96 ) * 32 + lane], h1);
    h1 = fmaxf(h1, 0.f);

    float h2 = b2[lane];
#pragma unroll
    for (int r = 0; r < 32; r++)
        h2 = fmaf(__shfl_sync(FULLM, h1, r), W2[r * 32 + lane], h2);
    h2 = fmaxf(h2, 0.f);

    float p = h2 * W3[lane];
#pragma unroll
    for (int off = 16; off > 0; off >>= 1)
        p += __shfl_xor_sync(FULLM, p, off);
    if (lane == 0) out[(size_t)4 * N_NODES] = p + b3[0];
}

// ---------------------------------------------------------------- launch
extern "C" void kernel_launch(void* const* d_in, const int* in_sizes, int n_in,
                              void* d_out, int out_size)
{
    const float* x    = (const float*)d_in[0];
    const int*   ei   = (const int*)  d_in[1];
    const float* aW   = (const float*)d_in[2];
    const float* ab   = (const float*)d_in[3];
    const float* aW1  = (const float*)d_in[4];
    const float* ab1  = (const float*)d_in[5];
    const float* aW2  = (const float*)d_in[6];
    const float* ab2  = (const float*)d_in[7];
    const float* aW3  = (const float*)d_in[8];
    const float* ab3  = (const float*)d_in[9];
    const float* cW   = (const float*)d_in[10];
    const float* cb   = (const float*)d_in[11];
    const float* cW1  = (const float*)d_in[12];
    const float* cb1  = (const float*)d_in[13];
    const float* cW2  = (const float*)d_in[14];
    const float* cb2  = (const float*)d_in[15];
    const float* cW3  = (const float*)d_in[16];
    const float* cb3  = (const float*)d_in[17];
    float* out = (float*)d_out;

    const int* src = ei;
    const int* dst = ei + N_EDGES;

    cudaFuncSetAttribute((const void*)k_gemm_fill,
                         cudaFuncAttributeMaxDynamicSharedMemorySize, SM_TOTAL_MMA);
    cudaFuncSetAttribute((const void*)k_mlp,
                         cudaFuncAttributeMaxDynamicSharedMemorySize, MLP_SMEM);

    k_init   <<<(N_NODES + 255) / 256, 256>>>();
    k_wprep  <<<(2 * CCH * CCH + 255) / 256, 256>>>(aW, cW);
    k_mlpprep<<<(32 * 128 + 32 * 32 + 8 * 32 + 255) / 256, 256>>>(aW1, aW2, aW3);
    k_degree <<<(N_EDGES + 255) / 256, 256>>>(dst);
    k_dinv   <<<(N_NODES + 255) / 256, 256>>>();
    k_scan1  <<<SCAN_G, SCAN_B>>>();
    k_scan2  <<<1, 128>>>();
    k_scan3  <<<SCAN_G, SCAN_B>>>();

    k_gemm_fill<<<2 * GEMM_BX + FILL_B, 256, SM_TOTAL_MMA>>>(x, src, dst);

    k_aggregate<<<2048, 256>>>(x, ab, cb);

    k_mlp<<<GEMM_BX, 128, MLP_SMEM>>>(ab1, ab2, ab3, out);

    k_value<<<1, 32>>>(cW1, cb1, cW2, cb2, cW3, cb3, out);
}

// round 12
// speedup vs baseline: 3.4586x; 1.1268x over previous
#include <cuda_runtime.h>
#include <cuda_fp16.h>
#include <stdint.h>
#include <math.h>

#define N_NODES 100000
#define N_EDGES 1600000
#define CCH 128
#define FULLM 0xffffffffu
#define SCAN_B 1024
#define SCAN_G ((N_NODES + SCAN_B - 1) / SCAN_B)   // 98
#define GEMM_BX ((N_NODES + 127) / 128)            // 782
#define FILL_B  ((N_EDGES + 255) / 256)            // 6250
#define WPREP_B 128                                // 2*128*128/256
#define MLPP_B  21                                 // ceil(5376/256)

// ---------------- device scratch (no allocation allowed) ----------------
__device__ uint4 g_feat_h[(size_t)N_NODES * 32];   // fp16 table: lane l = {actor 4l..4l+3, critic 4l..4l+3}
__device__ uint4 g_atab[(size_t)N_NODES * 16];     // fp16 actor activations a[N,128]
__device__ int   g_deg [N_NODES];                  // in-degree (excl self)
__device__ float g_dinv[N_NODES];
__device__ int   g_off [N_NODES + 1];
__device__ int   g_cur [N_NODES];
__device__ int   g_csr [N_EDGES];
__device__ int   g_bsum[SCAN_G];
__device__ float g_csum[CCH];
__device__ float g_wtf[2 * CCH * CCH];             // W^T tf32-rounded fp32: [half][n][k]
__device__ unsigned short g_w1t[32 * 128];         // W1^T fp16 [n][k]
__device__ unsigned short g_w2t[32 * 32];          // W2^T fp16 [n][k]
__device__ unsigned short g_w3t[8 * 32];           // W3^T fp16 [n][k], rows 4..7 zero

__device__ __forceinline__ unsigned int h2_as_u32(__half2 h) {
    return *reinterpret_cast<unsigned int*>(&h);
}
__device__ __forceinline__ uint32_t f2tf32(float f) {
    uint32_t r;
    asm("cvt.rna.tf32.f32 %0, %1;" : "=r"(r) : "f"(f));
    return r;
}

// ---------------------------------------------------------------- zero init
__global__ void k_init() {
    int i = blockIdx.x * blockDim.x + threadIdx.x;
    if (i < N_NODES) g_deg[i] = 0;
    if (blockIdx.x == 0 && threadIdx.x < CCH) g_csum[threadIdx.x] = 0.f;
}

// ---------------------------------------------------------------- degree + weight preps (fused, independent work)
__global__ void k_degree_prep(const int* __restrict__ dst,
                              const float* __restrict__ Wa, const float* __restrict__ Wc,
                              const float* __restrict__ W1, const float* __restrict__ W2,
                              const float* __restrict__ W3) {
    int b = blockIdx.x;
    if (b < FILL_B) {
        int i = b * 256 + threadIdx.x;
        if (i < N_EDGES) atomicAdd(&g_deg[dst[i]], 1);
        return;
    }
    b -= FILL_B;
    if (b < WPREP_B) {
        int idx = b * 256 + threadIdx.x;          // < 32768
        int h = idx >> 14;
        int rem = idx & 16383;
        int n = rem >> 7, k = rem & 127;
        const float* W = h ? Wc : Wa;
        g_wtf[idx] = __uint_as_float(f2tf32(W[k * CCH + n]));
        return;
    }
    b -= WPREP_B;
    int idx = b * 256 + threadIdx.x;
    if (idx < 32 * 128) {
        int n = idx >> 7, k = idx & 127;
        __half h = __float2half(W1[k * 32 + n]);
        g_w1t[idx] = *reinterpret_cast<unsigned short*>(&h);
    } else if (idx < 32 * 128 + 32 * 32) {
        int j = idx - 32 * 128;
        int n = j >> 5, k = j & 31;
        __half h = __float2half(W2[k * 32 + n]);
        g_w2t[j] = *reinterpret_cast<unsigned short*>(&h);
    } else if (idx < 32 * 128 + 32 * 32 + 8 * 32) {
        int j = idx - 32 * 128 - 32 * 32;
        int n = j >> 5, k = j & 31;
        float v = (n < 4) ? W3[k * 4 + n] : 0.f;
        __half h = __float2half(v);
        g_w3t[j] = *reinterpret_cast<unsigned short*>(&h);
    }
}

// ---------------- 3-phase parallel exclusive scan of deg (+ dinv in phase 1) ----------------
__device__ __forceinline__ int block_excl_scan(int v, int lane, int wid, int* warp_sums, int nwarp) {
    int inc = v;
#pragma unroll
    for (int o = 1; o < 32; o <<= 1) {
        int u = __shfl_up_sync(FULLM, inc, o);
        if (lane >= o) inc += u;
    }
    if (lane == 31) warp_sums[wid] = inc;
    __syncthreads();
    if (wid == 0) {
        int w = (lane < nwarp) ? warp_sums[lane] : 0;
#pragma unroll
        for (int o = 1; o < 32; o <<= 1) {
            int u = __shfl_up_sync(FULLM, w, o);
            if (lane >= o) w += u;
        }
        warp_sums[lane] = w;
    }
    __syncthreads();
    return (inc - v) + (wid ? warp_sums[wid - 1] : 0);
}
__global__ void k_scan1() {
    __shared__ int warp_sums[32];
    int i = blockIdx.x * SCAN_B + threadIdx.x;
    int d = (i < N_NODES) ? g_deg[i] : 0;
    if (i < N_NODES) g_dinv[i] = rsqrtf((float)(d + 1));
    int ex = block_excl_scan(d, threadIdx.x & 31, threadIdx.x >> 5, warp_sums, SCAN_B / 32);
    if (i < N_NODES) g_off[i] = ex;
    if (threadIdx.x == SCAN_B - 1) g_bsum[blockIdx.x] = ex + d;
}
__global__ void k_scan2() {
    __shared__ int warp_sums[32];
    int t = threadIdx.x;
    int v = (t < SCAN_G) ? g_bsum[t] : 0;
    int ex = block_excl_scan(v, t & 31, t >> 5, warp_sums, 4);
    if (t < SCAN_G) g_bsum[t] = ex;
}
__global__ void k_scan3() {
    int i = blockIdx.x * SCAN_B + threadIdx.x;
    if (i < N_NODES) {
        int o = g_off[i] + g_bsum[blockIdx.x];
        g_off[i] = o;
        g_cur[i] = o;
    }
    if (i == 0) g_off[N_NODES] = N_EDGES;
}

// ---------------------------------------------------------------- tf32 mma GEMM + CSR fill
#define KC 64
#define LDT 68                      // floats, smem row stride
#define SM_A 0                      // 128*68*4 = 34816
#define SM_B 34816
#define SM_TOTAL_MMA (2 * 34816)    // 69632 B

__device__ __forceinline__ void mma16808t(float c[4], const uint32_t a[4], const uint32_t b[2]) {
    asm volatile("mma.sync.aligned.m16n8k8.row.col.f32.tf32.tf32.f32 "
                 "{%0,%1,%2,%3}, {%4,%5,%6,%7}, {%8,%9}, {%0,%1,%2,%3};\n"
                 : "+f"(c[0]), "+f"(c[1]), "+f"(c[2]), "+f"(c[3])
                 : "r"(a[0]), "r"(a[1]), "r"(a[2]), "r"(a[3]), "r"(b[0]), "r"(b[1]));
}
__device__ __forceinline__ void mma16816h(float c[4], const uint32_t a[4], const uint32_t b[2]) {
    asm volatile("mma.sync.aligned.m16n8k16.row.col.f32.f16.f16.f32 "
                 "{%0,%1,%2,%3}, {%4,%5,%6,%7}, {%8,%9}, {%0,%1,%2,%3};\n"
                 : "+f"(c[0]), "+f"(c[1]), "+f"(c[2]), "+f"(c[3])
                 : "r"(a[0]), "r"(a[1]), "r"(a[2]), "r"(a[3]), "r"(b[0]), "r"(b[1]));
}

__global__ __launch_bounds__(256)
void k_gemm_fill(const float* __restrict__ x,
                 const int* __restrict__ src,
                 const int* __restrict__ dst)
{
    if (blockIdx.x >= 2 * GEMM_BX) {
        int e = (blockIdx.x - 2 * GEMM_BX) * 256 + threadIdx.x;
        if (e < N_EDGES) {
            int d = dst[e];
            int p = atomicAdd(&g_cur[d], 1);
            g_csr[p] = src[e];
        }
        return;
    }

    extern __shared__ char smem[];
    uint32_t* smA = reinterpret_cast<uint32_t*>(smem + SM_A);
    uint32_t* smB = reinterpret_cast<uint32_t*>(smem + SM_B);
    const int tid  = threadIdx.x;
    const int wid  = tid >> 5, lane = tid & 31;
    const int half = (blockIdx.x >= GEMM_BX) ? 1 : 0;
    const int bm   = (blockIdx.x - half * GEMM_BX) * 128;
    const int wm   = wid & 3;        // 32-row group
    const int wn   = wid >> 2;       // 64-col group
    const int lq   = lane >> 2;      // 0..7
    const int lr   = lane & 3;       // 0..3

    float acc[2][8][4];
#pragma unroll
    for (int i = 0; i < 2; i++)
#pragma unroll
        for (int j = 0; j < 8; j++)
#pragma unroll
            for (int q = 0; q < 4; q++) acc[i][j][q] = 0.f;

    for (int kc = 0; kc < CCH; kc += KC) {
        // A tile: 128 rows x 64 cols fp32 -> tf32
        for (int g = tid; g < 2048; g += 256) {
            int row = g >> 4, c4 = (g & 15) * 4;
            float4 v = make_float4(0.f, 0.f, 0.f, 0.f);
            if (bm + row < N_NODES)
                v = *reinterpret_cast<const float4*>(&x[(size_t)(bm + row) * CCH + kc + c4]);
            uint32_t* p = &smA[row * LDT + c4];
            p[0] = f2tf32(v.x); p[1] = f2tf32(v.y); p[2] = f2tf32(v.z); p[3] = f2tf32(v.w);
        }
        // B tile: 128 n x 64 k (already tf32-rounded)
        for (int g = tid; g < 2048; g += 256) {
            int n = g >> 4, c4 = (g & 15) * 4;
            const float4 v = *reinterpret_cast<const float4*>(
                &g_wtf[((size_t)(half * 128 + n)) * 128 + kc + c4]);
            uint32_t* p = &smB[n * LDT + c4];
            p[0] = __float_as_uint(v.x); p[1] = __float_as_uint(v.y);
            p[2] = __float_as_uint(v.z); p[3] = __float_as_uint(v.w);
        }
        __syncthreads();

#pragma unroll
        for (int ks = 0; ks < KC / 8; ks++) {
            const int k8 = ks * 8;
            uint32_t a[2][4];
#pragma unroll
            for (int ma = 0; ma < 2; ma++) {
                int r0 = wm * 32 + ma * 16 + lq;
                a[ma][0] = smA[r0 * LDT + k8 + lr];
                a[ma][1] = smA[(r0 + 8) * LDT + k8 + lr];
                a[ma][2] = smA[r0 * LDT + k8 + lr + 4];
                a[ma][3] = smA[(r0 + 8) * LDT + k8 + lr + 4];
            }
#pragma unroll
            for (int nb = 0; nb < 8; nb++) {
                int n = wn * 64 + nb * 8 + lq;
                uint32_t b[2];
                b[0] = smB[n * LDT + k8 + lr];
                b[1] = smB[n * LDT + k8 + lr + 4];
#pragma unroll
                for (int ma = 0; ma < 2; ma++) mma16808t(acc[ma][nb], a[ma], b);
            }
        }
        __syncthreads();
    }

    unsigned char* fb = reinterpret_cast<unsigned char*>(g_feat_h);
#pragma unroll
    for (int ma = 0; ma < 2; ma++) {
        int row0 = bm + wm * 32 + ma * 16 + lq;
        int row1 = row0 + 8;
        float dv0 = (row0 < N_NODES) ? g_dinv[row0] : 0.f;
        float dv1 = (row1 < N_NODES) ? g_dinv[row1] : 0.f;
#pragma unroll
        for (int nb = 0; nb < 8; nb++) {
            int cpair = wn * 32 + nb * 4 + lr;
            uint32_t cb = (uint32_t)(cpair >> 1) * 16 + (uint32_t)half * 8 + (cpair & 1) * 4;
            if (row0 < N_NODES) {
                *reinterpret_cast<uint32_t*>(fb + (size_t)row0 * 512 + cb) =
                    h2_as_u32(__floats2half2_rn(acc[ma][nb][0] * dv0, acc[ma][nb][1] * dv0));
            }
            if (row1 < N_NODES) {
                *reinterpret_cast<uint32_t*>(fb + (size_t)row1 * 512 + cb) =
                    h2_as_u32(__floats2half2_rn(acc[ma][nb][2] * dv1, acc[ma][nb][3] * dv1));
            }
        }
    }
}

// ---------------------------------------------------------------- gather + conv epilogue
__device__ __forceinline__ void addh(float4& A, float4& Cc, uint4 v) {
    float2 f0 = __half22float2(*reinterpret_cast<__half2*>(&v.x));
    float2 f1 = __half22float2(*reinterpret_cast<__half2*>(&v.y));
    float2 f2 = __half22float2(*reinterpret_cast<__half2*>(&v.z));
    float2 f3 = __half22float2(*reinterpret_cast<__half2*>(&v.w));
    A.x += f0.x; A.y += f0.y; A.z += f1.x; A.w += f1.y;
    Cc.x += f2.x; Cc.y += f2.y; Cc.z += f3.x; Cc.w += f3.y;
}

__global__ void k_aggregate(const float* __restrict__ x,
                            const float* __restrict__ a_conv_b,
                            const float* __restrict__ c_conv_b)
{
    __shared__ float sab[CCH], scb[CCH];
    __shared__ float scsum[CCH];

    const int tid = threadIdx.x;
    if (tid < 128) { sab[tid] = a_conv_b[tid]; scb[tid] = c_conv_b[tid]; scsum[tid] = 0.f; }
    __syncthreads();

    const int lane = tid & 31;
    const int warp = tid >> 5;
    const int gw = blockIdx.x * (blockDim.x >> 5) + warp;
    const int nw = gridDim.x * (blockDim.x >> 5);

    float4 cs = make_float4(0.f, 0.f, 0.f, 0.f);
    uint2* atab = reinterpret_cast<uint2*>(g_atab);

    for (int node = gw; node < N_NODES; node += nw) {
        const float dv = g_dinv[node];
        float4 A  = make_float4(0.f, 0.f, 0.f, 0.f);
        float4 Cc = make_float4(0.f, 0.f, 0.f, 0.f);
        addh(A, Cc, g_feat_h[(size_t)node * 32 + lane]);     // self loop

        const int beg = g_off[node], end = g_off[node + 1];
        int j = beg;
        for (; j + 3 < end; j += 4) {
            int s0 = g_csr[j], s1 = g_csr[j + 1], s2 = g_csr[j + 2], s3 = g_csr[j + 3];
            uint4 v0 = g_feat_h[(size_t)s0 * 32 + lane];
            uint4 v1 = g_feat_h[(size_t)s1 * 32 + lane];
            uint4 v2 = g_feat_h[(size_t)s2 * 32 + lane];
            uint4 v3 = g_feat_h[(size_t)s3 * 32 + lane];
            addh(A, Cc, v0); addh(A, Cc, v1); addh(A, Cc, v2); addh(A, Cc, v3);
        }
        for (; j < end; j++) {
            uint4 v0 = g_feat_h[(size_t)g_csr[j] * 32 + lane];
            addh(A, Cc, v0);
        }

        float4 xv = reinterpret_cast<const float4*>(x)[(size_t)node * 32 + lane];
        int c0 = 4 * lane;
        float4 a;
        a.x = fmaxf(fmaf(A.x, dv, sab[c0 + 0]), 0.f) + xv.x;
        a.y = fmaxf(fmaf(A.y, dv, sab[c0 + 1]), 0.f) + xv.y;
        a.z = fmaxf(fmaf(A.z, dv, sab[c0 + 2]), 0.f) + xv.z;
        a.w = fmaxf(fmaf(A.w, dv, sab[c0 + 3]), 0.f) + xv.w;

        uint2 av;
        av.x = h2_as_u32(__floats2half2_rn(a.x, a.y));
        av.y = h2_as_u32(__floats2half2_rn(a.z, a.w));
        atab[(size_t)node * 32 + lane] = av;

        cs.x += fmaxf(fmaf(Cc.x, dv, scb[c0 + 0]), 0.f) + xv.x;
        cs.y += fmaxf(fmaf(Cc.y, dv, scb[c0 + 1]), 0.f) + xv.y;
        cs.z += fmaxf(fmaf(Cc.z, dv, scb[c0 + 2]), 0.f) + xv.z;
        cs.w += fmaxf(fmaf(Cc.w, dv, scb[c0 + 3]), 0.f) + xv.w;
    }

    int c0 = 4 * lane;
    atomicAdd(&scsum[c0 + 0], cs.x);
    atomicAdd(&scsum[c0 + 1], cs.y);
    atomicAdd(&scsum[c0 + 2], cs.z);
    atomicAdd(&scsum[c0 + 3], cs.w);
    __syncthreads();
    if (tid < CCH) atomicAdd(&g_csum[tid], scsum[tid]);
}

// ---------------------------------------------------------------- actor MLP via mma.sync (+ critic head block)
#define MLP_LDA 136
#define MLP_LDH 40
#define OFF_A  0
#define OFF_H1 34816
#define OFF_H2 45056
#define OFF_W1 55296
#define OFF_W2 64000
#define OFF_W3 66560
#define OFF_B  67200
#define MLP_SMEM 67584

__device__ __forceinline__ float softplus_f(float v) {
    return fmaxf(v, 0.f) + log1pf(expf(-fabsf(v))) + 1e-20f;
}

__global__ __launch_bounds__(128)
void k_mlp(const float* __restrict__ b1, const float* __restrict__ b2,
           const float* __restrict__ b3,
           const float* __restrict__ cW1, const float* __restrict__ cb1,
           const float* __restrict__ cW2, const float* __restrict__ cb2,
           const float* __restrict__ cW3, const float* __restrict__ cb3,
           float* __restrict__ out)
{
    // last block: critic value head (one warp)
    if (blockIdx.x == GEMM_BX) {
        const int lane = threadIdx.x;
        if (lane >= 32) return;
        float c0 = g_csum[lane], c1 = g_csum[lane + 32],
              c2 = g_csum[lane + 64], c3 = g_csum[lane + 96];
        float h1 = cb1[lane];
#pragma unroll
        for (int r = 0; r < 32; r++)
            h1 = fmaf(__shfl_sync(FULLM, c0, r), cW1[(r      ) * 32 + lane], h1);
#pragma unroll
        for (int r = 0; r < 32; r++)
            h1 = fmaf(__shfl_sync(FULLM, c1, r), cW1[(r + 32 ) * 32 + lane], h1);
#pragma unroll
        for (int r = 0; r < 32; r++)
            h1 = fmaf(__shfl_sync(FULLM, c2, r), cW1[(r + 64 ) * 32 + lane], h1);
#pragma unroll
        for (int r = 0; r < 32; r++)
            h1 = fmaf(__shfl_sync(FULLM, c3, r), cW1[(r + 96 ) * 32 + lane], h1);
        h1 = fmaxf(h1, 0.f);
        float h2 = cb2[lane];
#pragma unroll
        for (int r = 0; r < 32; r++)
            h2 = fmaf(__shfl_sync(FULLM, h1, r), cW2[r * 32 + lane], h2);
        h2 = fmaxf(h2, 0.f);
        float p = h2 * cW3[lane];
#pragma unroll
        for (int off = 16; off > 0; off >>= 1)
            p += __shfl_xor_sync(FULLM, p, off);
        if (lane == 0) out[(size_t)4 * N_NODES] = p + cb3[0];
        return;
    }

    extern __shared__ char sm[];
    const int tid = threadIdx.x;
    const int w = tid >> 5, lane = tid & 31;
    const int lq = lane >> 2, lr = lane & 3;
    const int bm = blockIdx.x * 128;

    float* fb1 = reinterpret_cast<float*>(sm + OFF_B);
    float* fb2 = fb1 + 32;
    float* fb3 = fb2 + 32;

    for (int g = tid; g < 32 * 64; g += 128) {
        int n = g >> 6, k2 = g & 63;
        *reinterpret_cast<uint32_t*>(sm + OFF_W1 + n * (MLP_LDA * 2) + k2 * 4) =
            reinterpret_cast<const uint32_t*>(g_w1t)[n * 64 + k2];
    }
    for (int g = tid; g < 32 * 16; g += 128) {
        int n = g >> 4, k2 = g & 15;
        *reinterpret_cast<uint32_t*>(sm + OFF_W2 + n * (MLP_LDH * 2) + k2 * 4) =
            reinterpret_cast<const uint32_t*>(g_w2t)[n * 16 + k2];
    }
    if (tid < 128) {
        int n = tid >> 4, k2 = tid & 15;
        *reinterpret_cast<uint32_t*>(sm + OFF_W3 + n * (MLP_LDH * 2) + k2 * 4) =
            reinterpret_cast<const uint32_t*>(g_w3t)[n * 16 + k2];
    }
    if (tid < 32) { fb1[tid] = b1[tid]; fb2[tid] = b2[tid]; }
    if (tid < 4)  { fb3[tid] = b3[tid]; }
    for (int g = tid; g < 128 * 16; g += 128) {
        int row = g >> 4, q = g & 15;
        uint4 v = make_uint4(0u, 0u, 0u, 0u);
        if (bm + row < N_NODES) v = g_atab[(size_t)(bm + row) * 16 + q];
        *reinterpret_cast<uint4*>(sm + OFF_A + row * (MLP_LDA * 2) + q * 16) = v;
    }
    __syncthreads();

    float acc1[2][4][4];
#pragma unroll
    for (int i = 0; i < 2; i++)
#pragma unroll
        for (int j = 0; j < 4; j++)
#pragma unroll
            for (int q = 0; q < 4; q++) acc1[i][j][q] = 0.f;

#pragma unroll
    for (int ks = 0; ks < 8; ks++) {
        uint32_t a[2][4];
#pragma unroll
        for (int ma = 0; ma < 2; ma++) {
            int row = w * 32 + ma * 16 + lq;
            uint32_t o = OFF_A + row * (MLP_LDA * 2) + (ks * 16 + lr * 2) * 2;
            a[ma][0] = *reinterpret_cast<uint32_t*>(sm + o);
            a[ma][1] = *reinterpret_cast<uint32_t*>(sm + o + 8 * (MLP_LDA * 2));
            a[ma][2] = *reinterpret_cast<uint32_t*>(sm + o + 16);
            a[ma][3] = *reinterpret_cast<uint32_t*>(sm + o + 8 * (MLP_LDA * 2) + 16);
        }
#pragma unroll
        for (int nb = 0; nb < 4; nb++) {
            int n = nb * 8 + lq;
            uint32_t o = OFF_W1 + n * (MLP_LDA * 2) + (ks * 16 + lr * 2) * 2;
            uint32_t b[2];
            b[0] = *reinterpret_cast<uint32_t*>(sm + o);
            b[1] = *reinterpret_cast<uint32_t*>(sm + o + 16);
#pragma unroll
            for (int ma = 0; ma < 2; ma++) mma16816h(acc1[ma][nb], a[ma], b);
        }
    }
#pragma unroll
    for (int ma = 0; ma < 2; ma++) {
        int row = w * 32 + ma * 16 + lq;
#pragma unroll
        for (int nb = 0; nb < 4; nb++) {
            int col = nb * 8 + lr * 2;
            float v0 = fmaxf(acc1[ma][nb][0] + fb1[col], 0.f);
            float v1 = fmaxf(acc1[ma][nb][1] + fb1[col + 1], 0.f);
            float v2 = fmaxf(acc1[ma][nb][2] + fb1[col], 0.f);
            float v3 = fmaxf(acc1[ma][nb][3] + fb1[col + 1], 0.f);
            *reinterpret_cast<uint32_t*>(sm + OFF_H1 + row * (MLP_LDH * 2) + col * 2) =
                h2_as_u32(__floats2half2_rn(v0, v1));
            *reinterpret_cast<uint32_t*>(sm + OFF_H1 + (row + 8) * (MLP_LDH * 2) + col * 2) =
                h2_as_u32(__floats2half2_rn(v2, v3));
        }
    }
    __syncwarp();

    float acc2[2][4][4];
#pragma unroll
    for (int i = 0; i < 2; i++)
#pragma unroll
        for (int j = 0; j < 4; j++)
#pragma unroll
            for (int q = 0; q < 4; q++) acc2[i][j][q] = 0.f;
#pragma unroll
    for (int ks = 0; ks < 2; ks++) {
        uint32_t a[2][4];
#pragma unroll
        for (int ma = 0; ma < 2; ma++) {
            int row = w * 32 + ma * 16 + lq;
            uint32_t o = OFF_H1 + row * (MLP_LDH * 2) + (ks * 16 + lr * 2) * 2;
            a[ma][0] = *reinterpret_cast<uint32_t*>(sm + o);
            a[ma][1] = *reinterpret_cast<uint32_t*>(sm + o + 8 * (MLP_LDH * 2));
            a[ma][2] = *reinterpret_cast<uint32_t*>(sm + o + 16);
            a[ma][3] = *reinterpret_cast<uint32_t*>(sm + o + 8 * (MLP_LDH * 2) + 16);
        }
#pragma unroll
        for (int nb = 0; nb < 4; nb++) {
            int n = nb * 8 + lq;
            uint32_t o = OFF_W2 + n * (MLP_LDH * 2) + (ks * 16 + lr * 2) * 2;
            uint32_t b[2];
            b[0] = *reinterpret_cast<uint32_t*>(sm + o);
            b[1] = *reinterpret_cast<uint32_t*>(sm + o + 16);
#pragma unroll
            for (int ma = 0; ma < 2; ma++) mma16816h(acc2[ma][nb], a[ma], b);
        }
    }
#pragma unroll
    for (int ma = 0; ma < 2; ma++) {
        int row = w * 32 + ma * 16 + lq;
#pragma unroll
        for (int nb = 0; nb < 4; nb++) {
            int col = nb * 8 + lr * 2;
            float v0 = fmaxf(acc2[ma][nb][0] + fb2[col], 0.f);
            float v1 = fmaxf(acc2[ma][nb][1] + fb2[col + 1], 0.f);
            float v2 = fmaxf(acc2[ma][nb][2] + fb2[col], 0.f);
            float v3 = fmaxf(acc2[ma][nb][3] + fb2[col + 1], 0.f);
            *reinterpret_cast<uint32_t*>(sm + OFF_H2 + row * (MLP_LDH * 2) + col * 2) =
                h2_as_u32(__floats2half2_rn(v0, v1));
            *reinterpret_cast<uint32_t*>(sm + OFF_H2 + (row + 8) * (MLP_LDH * 2) + col * 2) =
                h2_as_u32(__floats2half2_rn(v2, v3));
        }
    }
    __syncwarp();

    float acc3[2][4];
#pragma unroll
    for (int i = 0; i < 2; i++)
#pragma unroll
        for (int q = 0; q < 4; q++) acc3[i][q] = 0.f;
#pragma unroll
    for (int ks = 0; ks < 2; ks++) {
        uint32_t a[2][4];
#pragma unroll
        for (int ma = 0; ma < 2; ma++) {
            int row = w * 32 + ma * 16 + lq;
            uint32_t o = OFF_H2 + row * (MLP_LDH * 2) + (ks * 16 + lr * 2) * 2;
            a[ma][0] = *reinterpret_cast<uint32_t*>(sm + o);
            a[ma][1] = *reinterpret_cast<uint32_t*>(sm + o + 8 * (MLP_LDH * 2));
            a[ma][2] = *reinterpret_cast<uint32_t*>(sm + o + 16);
            a[ma][3] = *reinterpret_cast<uint32_t*>(sm + o + 8 * (MLP_LDH * 2) + 16);
        }
        int n = lq;
        uint32_t o = OFF_W3 + n * (MLP_LDH * 2) + (ks * 16 + lr * 2) * 2;
        uint32_t b[2];
        b[0] = *reinterpret_cast<uint32_t*>(sm + o);
        b[1] = *reinterpret_cast<uint32_t*>(sm + o + 16);
#pragma unroll
        for (int ma = 0; ma < 2; ma++) mma16816h(acc3[ma], a[ma], b);
    }
    if (lr < 2) {
        int ca = 2 * lr, cb = 2 * lr + 1;
#pragma unroll
        for (int ma = 0; ma < 2; ma++) {
            int r0 = bm + w * 32 + ma * 16 + lq;
            int r1 = r0 + 8;
            if (r0 < N_NODES) {
                float s0 = softplus_f(acc3[ma][0] + fb3[ca]);
                float s1 = softplus_f(acc3[ma][1] + fb3[cb]);
                if (ca == 0) out[r0] = s0; else out[N_NODES + (size_t)r0 * 3 + ca - 1] = s0;
                out[N_NODES + (size_t)r0 * 3 + cb - 1] = s1;
            }
            if (r1 < N_NODES) {
                float s2 = softplus_f(acc3[ma][2] + fb3[ca]);
                float s3 = softplus_f(acc3[ma][3] + fb3[cb]);
                if (ca == 0) out[r1] = s2; else out[N_NODES + (size_t)r1 * 3 + ca - 1] = s2;
                out[N_NODES + (size_t)r1 * 3 + cb - 1] = s3;
            }
        }
    }
}

// ---------------------------------------------------------------- launch
extern "C" void kernel_launch(void* const* d_in, const int* in_sizes, int n_in,
                              void* d_out, int out_size)
{
    const float* x    = (const float*)d_in[0];
    const int*   ei   = (const int*)  d_in[1];
    const float* aW   = (const float*)d_in[2];
    const float* ab   = (const float*)d_in[3];
    const float* aW1  = (const float*)d_in[4];
    const float* ab1  = (const float*)d_in[5];
    const float* aW2  = (const float*)d_in[6];
    const float* ab2  = (const float*)d_in[7];
    const float* aW3  = (const float*)d_in[8];
    const float* ab3  = (const float*)d_in[9];
    const float* cW   = (const float*)d_in[10];
    const float* cb   = (const float*)d_in[11];
    const float* cW1  = (const float*)d_in[12];
    const float* cb1  = (const float*)d_in[13];
    const float* cW2  = (const float*)d_in[14];
    const float* cb2  = (const float*)d_in[15];
    const float* cW3  = (const float*)d_in[16];
    const float* cb3  = (const float*)d_in[17];
    float* out = (float*)d_out;

    const int* src = ei;
    const int* dst = ei + N_EDGES;

    cudaFuncSetAttribute((const void*)k_gemm_fill,
                         cudaFuncAttributeMaxDynamicSharedMemorySize, SM_TOTAL_MMA);
    cudaFuncSetAttribute((const void*)k_mlp,
                         cudaFuncAttributeMaxDynamicSharedMemorySize, MLP_SMEM);

    k_init       <<<(N_NODES + 255) / 256, 256>>>();
    k_degree_prep<<<FILL_B + WPREP_B + MLPP_B, 256>>>(dst, aW, cW, aW1, aW2, aW3);
    k_scan1      <<<SCAN_G, SCAN_B>>>();
    k_scan2      <<<1, 128>>>();
    k_scan3      <<<SCAN_G, SCAN_B>>>();

    k_gemm_fill<<<2 * GEMM_BX + FILL_B, 256, SM_TOTAL_MMA>>>(x, src, dst);

    k_aggregate<<<2048, 256>>>(x, ab, cb);

    k_mlp<<<GEMM_BX + 1, 128, MLP_SMEM>>>(ab1, ab2, ab3,
                                          cW1, cb1, cW2, cb2, cW3, cb3, out);
}